// round 1
// baseline (speedup 1.0000x reference)
#include <cuda_runtime.h>

#define NTOK 8192
#define DIN  1024
#define DH   128

// Scratch for Q, K, V projections (device globals — no allocation allowed).
__device__ float g_Q[NTOK * DH];
__device__ float g_K[NTOK * DH];
__device__ float g_V[NTOK * DH];

// ---------------------------------------------------------------------------
// Kernel 1: QKV projection.  out[m, c] = sum_k x[m, k] * W[k, c]
// BM=64 rows, full BN=128 cols, BK=32.  256 threads, 4x8 microtile/thread.
// grid = (NTOK/64, 3): blockIdx.y selects Wq/Wk/Wv.
// ---------------------------------------------------------------------------
__global__ __launch_bounds__(256) void qkv_proj_kernel(
    const float* __restrict__ x,
    const float* __restrict__ Wq,
    const float* __restrict__ Wk,
    const float* __restrict__ Wv) {
  __shared__ float Xs[64 * 33];    // [r][kk], stride 33 (pad vs bank conflict)
  __shared__ float Ws[32 * 128];   // [kk][c]

  const float* W;
  float* out;
  if (blockIdx.y == 0)      { W = Wq; out = g_Q; }
  else if (blockIdx.y == 1) { W = Wk; out = g_K; }
  else                      { W = Wv; out = g_V; }

  const int tid = threadIdx.x;
  const int tx = tid & 15;        // 0..15 -> 8 output cols each
  const int ty = tid >> 4;        // 0..15 -> 4 output rows each
  const int m0 = blockIdx.x * 64;

  float acc[4][8];
#pragma unroll
  for (int i = 0; i < 4; i++)
#pragma unroll
    for (int j = 0; j < 8; j++) acc[i][j] = 0.f;

  for (int k0 = 0; k0 < DIN; k0 += 32) {
    __syncthreads();
    // Load x tile 64x32 (coalesced: 32 lanes cover one 128B row-chunk).
#pragma unroll
    for (int i = 0; i < 8; i++) {
      int e = tid + i * 256;
      int r = e >> 5, kk = e & 31;
      Xs[r * 33 + kk] = x[(size_t)(m0 + r) * DIN + k0 + kk];
    }
    // Load W tile 32x128 as float4 (coalesced).
#pragma unroll
    for (int i = 0; i < 4; i++) {
      int e = tid + i * 256;
      int c4 = e & 31, kk = e >> 5;
      *(float4*)&Ws[kk * 128 + c4 * 4] =
          *(const float4*)&W[(size_t)(k0 + kk) * DH + c4 * 4];
    }
    __syncthreads();

#pragma unroll 8
    for (int kk = 0; kk < 32; kk++) {
      float a[4];
#pragma unroll
      for (int i = 0; i < 4; i++) a[i] = Xs[(4 * ty + i) * 33 + kk];
      float4 b0 = *(float4*)&Ws[kk * 128 + 8 * tx];
      float4 b1 = *(float4*)&Ws[kk * 128 + 8 * tx + 4];
#pragma unroll
      for (int i = 0; i < 4; i++) {
        acc[i][0] += a[i] * b0.x;  acc[i][1] += a[i] * b0.y;
        acc[i][2] += a[i] * b0.z;  acc[i][3] += a[i] * b0.w;
        acc[i][4] += a[i] * b1.x;  acc[i][5] += a[i] * b1.y;
        acc[i][6] += a[i] * b1.z;  acc[i][7] += a[i] * b1.w;
      }
    }
  }

#pragma unroll
  for (int i = 0; i < 4; i++) {
    float4 r0 = make_float4(acc[i][0], acc[i][1], acc[i][2], acc[i][3]);
    float4 r1 = make_float4(acc[i][4], acc[i][5], acc[i][6], acc[i][7]);
    size_t base = (size_t)(m0 + 4 * ty + i) * DH + 8 * tx;
    *(float4*)&out[base]     = r0;
    *(float4*)&out[base + 4] = r1;
  }
}

// ---------------------------------------------------------------------------
// Kernel 2: flash attention over the full N=8192 sequence.
// BM=64 query rows per CTA, BN=64 keys per tile, d=128.
// 256 threads as a 16x16 grid: S microtile 4x4, O microtile 4x8.
// Online softmax with per-row (m, l) carried in registers, reduced across the
// 16-lane tx group with shuffles.
// ---------------------------------------------------------------------------
__global__ __launch_bounds__(256) void flash_kernel(float* __restrict__ out) {
  extern __shared__ float sm[];
  float* Qs = sm;                    // [64][129]
  float* Ks = Qs + 64 * 129;         // [64][129]
  float* Vs = Ks + 64 * 129;         // [64][132] (stride mult of 4 for float4)
  float* Ps = Vs + 64 * 132;         // [64][65]

  const int tid = threadIdx.x;
  const int tx = tid & 15;
  const int ty = tid >> 4;
  const int m0 = blockIdx.x * 64;
  const float SCALE = 0.08838834764831845f;   // 1/sqrt(128)
  const unsigned FULL = 0xffffffffu;

  // Load Q tile once (coalesced).
#pragma unroll
  for (int i = 0; i < 32; i++) {
    int e = tid + i * 256;
    int r = e >> 7, d = e & 127;
    Qs[r * 129 + d] = g_Q[(size_t)(m0 + r) * DH + d];
  }

  float o[4][8];
#pragma unroll
  for (int i = 0; i < 4; i++)
#pragma unroll
    for (int j = 0; j < 8; j++) o[i][j] = 0.f;
  float mrow[4], lrow[4];
#pragma unroll
  for (int i = 0; i < 4; i++) { mrow[i] = -1e30f; lrow[i] = 0.f; }

  for (int n0 = 0; n0 < NTOK; n0 += 64) {
    __syncthreads();   // prev iter done with Ks/Vs/Ps
#pragma unroll
    for (int i = 0; i < 32; i++) {
      int e = tid + i * 256;
      int r = e >> 7, d = e & 127;
      Ks[r * 129 + d] = g_K[(size_t)(n0 + r) * DH + d];
      Vs[r * 132 + d] = g_V[(size_t)(n0 + r) * DH + d];
    }
    __syncthreads();

    // S = Q K^T  (4x4 per thread)
    float s[4][4];
#pragma unroll
    for (int i = 0; i < 4; i++)
#pragma unroll
      for (int j = 0; j < 4; j++) s[i][j] = 0.f;

#pragma unroll 4
    for (int d = 0; d < 128; d++) {
      float a[4], b[4];
#pragma unroll
      for (int i = 0; i < 4; i++) a[i] = Qs[(4 * ty + i) * 129 + d];
#pragma unroll
      for (int j = 0; j < 4; j++) b[j] = Ks[(4 * tx + j) * 129 + d];
#pragma unroll
      for (int i = 0; i < 4; i++)
#pragma unroll
        for (int j = 0; j < 4; j++) s[i][j] += a[i] * b[j];
    }

    // Online softmax per row (rows owned by fixed ty; reduce across tx group).
#pragma unroll
    for (int i = 0; i < 4; i++) {
#pragma unroll
      for (int j = 0; j < 4; j++) s[i][j] *= SCALE;
      float mx = fmaxf(fmaxf(s[i][0], s[i][1]), fmaxf(s[i][2], s[i][3]));
#pragma unroll
      for (int off = 1; off < 16; off <<= 1)
        mx = fmaxf(mx, __shfl_xor_sync(FULL, mx, off));
      float mnew = fmaxf(mrow[i], mx);
      float alpha = __expf(mrow[i] - mnew);
      mrow[i] = mnew;
      float sum = 0.f;
#pragma unroll
      for (int j = 0; j < 4; j++) {
        float p = __expf(s[i][j] - mnew);
        s[i][j] = p;
        sum += p;
      }
#pragma unroll
      for (int off = 1; off < 16; off <<= 1)
        sum += __shfl_xor_sync(FULL, sum, off);
      lrow[i] = lrow[i] * alpha + sum;
#pragma unroll
      for (int j = 0; j < 8; j++) o[i][j] *= alpha;
    }

    // Stage P to shared for the PV GEMM.
#pragma unroll
    for (int i = 0; i < 4; i++)
#pragma unroll
      for (int j = 0; j < 4; j++)
        Ps[(4 * ty + i) * 65 + 4 * tx + j] = s[i][j];
    __syncthreads();

    // O += P * V   (4 rows x 8 cols per thread, cols = 8*tx..8*tx+7)
#pragma unroll 8
    for (int k = 0; k < 64; k++) {
      float4 v0 = *(float4*)&Vs[k * 132 + 8 * tx];
      float4 v1 = *(float4*)&Vs[k * 132 + 8 * tx + 4];
#pragma unroll
      for (int i = 0; i < 4; i++) {
        float p = Ps[(4 * ty + i) * 65 + k];
        o[i][0] += p * v0.x;  o[i][1] += p * v0.y;
        o[i][2] += p * v0.z;  o[i][3] += p * v0.w;
        o[i][4] += p * v1.x;  o[i][5] += p * v1.y;
        o[i][6] += p * v1.z;  o[i][7] += p * v1.w;
      }
    }
  }

  // Normalize and write out.
#pragma unroll
  for (int i = 0; i < 4; i++) {
    float inv = 1.0f / lrow[i];
    float4 r0 = make_float4(o[i][0] * inv, o[i][1] * inv,
                            o[i][2] * inv, o[i][3] * inv);
    float4 r1 = make_float4(o[i][4] * inv, o[i][5] * inv,
                            o[i][6] * inv, o[i][7] * inv);
    size_t base = (size_t)(m0 + 4 * ty + i) * DH + 8 * tx;
    *(float4*)&out[base]     = r0;
    *(float4*)&out[base + 4] = r1;
  }
}

// ---------------------------------------------------------------------------
extern "C" void kernel_launch(void* const* d_in, const int* in_sizes, int n_in,
                              void* d_out, int out_size) {
  const float* x  = (const float*)d_in[0];
  const float* Wq = (const float*)d_in[1];
  const float* Wk = (const float*)d_in[2];
  const float* Wv = (const float*)d_in[3];
  float* out = (float*)d_out;

  qkv_proj_kernel<<<dim3(NTOK / 64, 3, 1), 256>>>(x, Wq, Wk, Wv);

  const size_t smem_bytes =
      (size_t)(64 * 129 + 64 * 129 + 64 * 132 + 64 * 65) * sizeof(float);
  cudaFuncSetAttribute(flash_kernel,
                       cudaFuncAttributeMaxDynamicSharedMemorySize,
                       (int)smem_bytes);
  flash_kernel<<<NTOK / 64, 256, smem_bytes>>>(out);
}

// round 3
// speedup vs baseline: 2.4684x; 2.4684x over previous
#include <cuda_runtime.h>
#include <cuda_bf16.h>
#include <cuda_fp16.h>
#include <cstdint>

#define NTOK 8192
#define DIN  1024
#define DH   128

// Split operands produced by the projection kernel.
__device__ __nv_bfloat16 g_Qhi[NTOK * DH], g_Qlo[NTOK * DH]; // pre-scaled by (1/sqrt d)*log2 e
__device__ __nv_bfloat16 g_Khi[NTOK * DH], g_Klo[NTOK * DH];
__device__ __half        g_Vhi[NTOK * DH], g_Vlo[NTOK * DH];

__device__ __forceinline__ uint32_t smem_u32(const void* p) {
  uint32_t a;
  asm("{ .reg .u64 t; cvta.to.shared.u64 t, %1; cvt.u32.u64 %0, t; }"
      : "=r"(a) : "l"(p));
  return a;
}
__device__ __forceinline__ float ex2f(float x) {
  float y; asm("ex2.approx.ftz.f32 %0, %1;" : "=f"(y) : "f"(x)); return y;
}
__device__ __forceinline__ void ldsm4(uint32_t* r, uint32_t addr) {
  asm volatile("ldmatrix.sync.aligned.m8n8.x4.shared.b16 {%0,%1,%2,%3}, [%4];"
               : "=r"(r[0]), "=r"(r[1]), "=r"(r[2]), "=r"(r[3]) : "r"(addr));
}
__device__ __forceinline__ void ldsm4t(uint32_t* r, uint32_t addr) {
  asm volatile("ldmatrix.sync.aligned.m8n8.x4.trans.shared.b16 {%0,%1,%2,%3}, [%4];"
               : "=r"(r[0]), "=r"(r[1]), "=r"(r[2]), "=r"(r[3]) : "r"(addr));
}
__device__ __forceinline__ void mma_bf16(float* d, const uint32_t* a,
                                         const uint32_t* b) {
  asm volatile(
      "mma.sync.aligned.m16n8k16.row.col.f32.bf16.bf16.f32 "
      "{%0,%1,%2,%3}, {%4,%5,%6,%7}, {%8,%9}, {%0,%1,%2,%3};"
      : "+f"(d[0]), "+f"(d[1]), "+f"(d[2]), "+f"(d[3])
      : "r"(a[0]), "r"(a[1]), "r"(a[2]), "r"(a[3]), "r"(b[0]), "r"(b[1]));
}
__device__ __forceinline__ void mma_f16(float* d, const uint32_t* a,
                                        const uint32_t* b) {
  asm volatile(
      "mma.sync.aligned.m16n8k16.row.col.f32.f16.f16.f32 "
      "{%0,%1,%2,%3}, {%4,%5,%6,%7}, {%8,%9}, {%0,%1,%2,%3};"
      : "+f"(d[0]), "+f"(d[1]), "+f"(d[2]), "+f"(d[3])
      : "r"(a[0]), "r"(a[1]), "r"(a[2]), "r"(a[3]), "r"(b[0]), "r"(b[1]));
}
__device__ __forceinline__ void pack_h2(float x, float y, uint32_t& hi,
                                        uint32_t& lo) {
  __half2 h = __floats2half2_rn(x, y);
  float2 b = __half22float2(h);
  __half2 l = __floats2half2_rn(x - b.x, y - b.y);
  hi = *(uint32_t*)&h;
  lo = *(uint32_t*)&l;
}

// ---------------------------------------------------------------------------
// Kernel 1: QKV projection (fp32 CUDA-core) -> split bf16/fp16 outputs.
// ---------------------------------------------------------------------------
__global__ __launch_bounds__(256) void qkv_proj_kernel(
    const float* __restrict__ x,
    const float* __restrict__ Wq,
    const float* __restrict__ Wk,
    const float* __restrict__ Wv) {
  __shared__ float Xs[64 * 33];
  __shared__ float Ws[32 * 128];

  const float* W;
  if (blockIdx.y == 0)      W = Wq;
  else if (blockIdx.y == 1) W = Wk;
  else                      W = Wv;

  const int tid = threadIdx.x;
  const int tx = tid & 15;
  const int ty = tid >> 4;
  const int m0 = blockIdx.x * 64;

  float acc[4][8];
#pragma unroll
  for (int i = 0; i < 4; i++)
#pragma unroll
    for (int j = 0; j < 8; j++) acc[i][j] = 0.f;

  for (int k0 = 0; k0 < DIN; k0 += 32) {
    __syncthreads();
#pragma unroll
    for (int i = 0; i < 8; i++) {
      int e = tid + i * 256;
      int r = e >> 5, kk = e & 31;
      Xs[r * 33 + kk] = x[(size_t)(m0 + r) * DIN + k0 + kk];
    }
#pragma unroll
    for (int i = 0; i < 4; i++) {
      int e = tid + i * 256;
      int c4 = e & 31, kk = e >> 5;
      *(float4*)&Ws[kk * 128 + c4 * 4] =
          *(const float4*)&W[(size_t)(k0 + kk) * DH + c4 * 4];
    }
    __syncthreads();

#pragma unroll 8
    for (int kk = 0; kk < 32; kk++) {
      float a[4];
#pragma unroll
      for (int i = 0; i < 4; i++) a[i] = Xs[(4 * ty + i) * 33 + kk];
      float4 b0 = *(float4*)&Ws[kk * 128 + 8 * tx];
      float4 b1 = *(float4*)&Ws[kk * 128 + 8 * tx + 4];
#pragma unroll
      for (int i = 0; i < 4; i++) {
        acc[i][0] += a[i] * b0.x;  acc[i][1] += a[i] * b0.y;
        acc[i][2] += a[i] * b0.z;  acc[i][3] += a[i] * b0.w;
        acc[i][4] += a[i] * b1.x;  acc[i][5] += a[i] * b1.y;
        acc[i][6] += a[i] * b1.z;  acc[i][7] += a[i] * b1.w;
      }
    }
  }

  const float QSCALE = 0.08838834764831845f * 1.4426950408889634f;

#pragma unroll
  for (int i = 0; i < 4; i++) {
    int m = m0 + 4 * ty + i;
#pragma unroll
    for (int j = 0; j < 8; j++) {
      int c = 8 * tx + j;
      float v = acc[i][j];
      size_t idx = (size_t)m * DH + c;
      if (blockIdx.y == 0) {
        v *= QSCALE;
        __nv_bfloat16 hi = __float2bfloat16_rn(v);
        g_Qhi[idx] = hi;
        g_Qlo[idx] = __float2bfloat16_rn(v - __bfloat162float(hi));
      } else if (blockIdx.y == 1) {
        __nv_bfloat16 hi = __float2bfloat16_rn(v);
        g_Khi[idx] = hi;
        g_Klo[idx] = __float2bfloat16_rn(v - __bfloat162float(hi));
      } else {
        __half hi = __float2half_rn(v);
        g_Vhi[idx] = hi;
        g_Vlo[idx] = __float2half_rn(v - __half2float(hi));
      }
    }
  }
}

// ---------------------------------------------------------------------------
// Kernel 2: FA2-style flash attention on mma.sync (HMMA).
// BM=64 queries/CTA (4 warps x 16 rows), BN=64 keys per iteration, d=128.
// SMEM: Khi, Klo (bf16) and Vhi, Vlo (fp16), each [64][136] padded rows.
// ---------------------------------------------------------------------------
#define ROWB 272           // bytes per padded smem row (136 halves)
#define KHI 0
#define KLO 17408
#define VHI 34816
#define VLO 52224
#define SMEM_FLASH (4 * 17408)

__global__ __launch_bounds__(128) void flash_mma(float* __restrict__ out) {
  extern __shared__ char smc[];
  const int tid = threadIdx.x;
  const int lane = tid & 31, warp = tid >> 5;
  const int wm = warp * 16;
  const int m0 = blockIdx.x * 64;
  const uint32_t sb = smem_u32(smc);

  // --- Stage Q (hi->KHI, lo->KLO), build resident A fragments ---
#pragma unroll
  for (int it = 0; it < 8; it++) {
    int idx = tid + it * 128;
    int r = idx >> 4, c = idx & 15;
    size_t g = (size_t)(m0 + r) * DH + c * 8;
    *(float4*)(smc + KHI + r * ROWB + c * 16) = *(const float4*)(g_Qhi + g);
    *(float4*)(smc + KLO + r * ROWB + c * 16) = *(const float4*)(g_Qlo + g);
  }
  __syncthreads();

  uint32_t qh[8][4], ql[8][4];
  {
    uint32_t aoff = (uint32_t)(wm + (lane & 15)) * ROWB + (lane >> 4) * 16;
#pragma unroll
    for (int j = 0; j < 8; j++) {
      ldsm4(qh[j], sb + KHI + aoff + j * 32);
      ldsm4(ql[j], sb + KLO + aoff + j * 32);
    }
  }
  __syncthreads();

  float of[16][4];
#pragma unroll
  for (int f = 0; f < 16; f++)
#pragma unroll
    for (int e = 0; e < 4; e++) of[f][e] = 0.f;
  float mrow0 = -1e30f, mrow1 = -1e30f, l0 = 0.f, l1 = 0.f;

  // Precomputed ldmatrix address pieces.
  const uint32_t sb_addr = sb + (uint32_t)((lane & 7) + ((lane >> 4) << 3)) * ROWB +
                           ((lane >> 3) & 1) * 16;           // S B-load (non-trans)
  const uint32_t vb_addr = sb + (uint32_t)((lane & 7) + (((lane >> 3) & 1) << 3)) * ROWB +
                           ((lane >> 4) & 1) * 16;           // PV B-load (trans)

  for (int tile = 0; tile < NTOK / 64; tile++) {
    const int n0 = tile * 64;
    // ---- load K/V tile ----
#pragma unroll
    for (int it = 0; it < 8; it++) {
      int idx = tid + it * 128;
      int r = idx >> 4, c = idx & 15;
      size_t g = (size_t)(n0 + r) * DH + c * 8;
      uint32_t d = r * ROWB + c * 16;
      *(float4*)(smc + KHI + d) = *(const float4*)(g_Khi + g);
      *(float4*)(smc + KLO + d) = *(const float4*)(g_Klo + g);
      *(float4*)(smc + VHI + d) = *(const float4*)(g_Vhi + g);
      *(float4*)(smc + VLO + d) = *(const float4*)(g_Vlo + g);
    }
    __syncthreads();

    // ---- S = Q K^T (16x64 per warp) ----
    float sf[8][4];
#pragma unroll
    for (int f = 0; f < 8; f++)
#pragma unroll
      for (int e = 0; e < 4; e++) sf[f][e] = 0.f;

#pragma unroll
    for (int j = 0; j < 8; j++) {
#pragma unroll
      for (int f2 = 0; f2 < 4; f2++) {
        uint32_t bh[4], bl[4];
        uint32_t a = sb_addr + (uint32_t)(f2 * 16) * ROWB + j * 32;
        ldsm4(bh, KHI + a);
        ldsm4(bl, KLO + a);
        mma_bf16(sf[2 * f2], qh[j], bh);
        mma_bf16(sf[2 * f2], qh[j], bl);
        mma_bf16(sf[2 * f2], ql[j], bh);
        mma_bf16(sf[2 * f2 + 1], qh[j], bh + 2);
        mma_bf16(sf[2 * f2 + 1], qh[j], bl + 2);
        mma_bf16(sf[2 * f2 + 1], ql[j], bh + 2);
      }
    }

    // ---- online softmax (rows r0=lane>>2, r1=r0+8; base-2 logits) ----
    float mx0 = sf[0][0], mx1 = sf[0][2];
#pragma unroll
    for (int f = 0; f < 8; f++) {
      mx0 = fmaxf(mx0, fmaxf(sf[f][0], sf[f][1]));
      mx1 = fmaxf(mx1, fmaxf(sf[f][2], sf[f][3]));
    }
    mx0 = fmaxf(mx0, __shfl_xor_sync(0xffffffffu, mx0, 1));
    mx0 = fmaxf(mx0, __shfl_xor_sync(0xffffffffu, mx0, 2));
    mx1 = fmaxf(mx1, __shfl_xor_sync(0xffffffffu, mx1, 1));
    mx1 = fmaxf(mx1, __shfl_xor_sync(0xffffffffu, mx1, 2));

    float mn0 = fmaxf(mrow0, mx0), mn1 = fmaxf(mrow1, mx1);
    float a0 = ex2f(mrow0 - mn0), a1 = ex2f(mrow1 - mn1);
    mrow0 = mn0; mrow1 = mn1;

    float s0 = 0.f, s1 = 0.f;
#pragma unroll
    for (int f = 0; f < 8; f++) {
      sf[f][0] = ex2f(sf[f][0] - mn0);
      sf[f][1] = ex2f(sf[f][1] - mn0);
      sf[f][2] = ex2f(sf[f][2] - mn1);
      sf[f][3] = ex2f(sf[f][3] - mn1);
      s0 += sf[f][0] + sf[f][1];
      s1 += sf[f][2] + sf[f][3];
    }
    s0 += __shfl_xor_sync(0xffffffffu, s0, 1);
    s0 += __shfl_xor_sync(0xffffffffu, s0, 2);
    s1 += __shfl_xor_sync(0xffffffffu, s1, 1);
    s1 += __shfl_xor_sync(0xffffffffu, s1, 2);
    l0 = l0 * a0 + s0;
    l1 = l1 * a1 + s1;

#pragma unroll
    for (int f = 0; f < 16; f++) {
      of[f][0] *= a0;  of[f][1] *= a0;
      of[f][2] *= a1;  of[f][3] *= a1;
    }

    // ---- convert P to fp16 hi/lo A-fragments (registers only) ----
    uint32_t ph[4][4], pl[4][4];
#pragma unroll
    for (int j2 = 0; j2 < 4; j2++) {
      pack_h2(sf[2 * j2][0],     sf[2 * j2][1],     ph[j2][0], pl[j2][0]);
      pack_h2(sf[2 * j2][2],     sf[2 * j2][3],     ph[j2][1], pl[j2][1]);
      pack_h2(sf[2 * j2 + 1][0], sf[2 * j2 + 1][1], ph[j2][2], pl[j2][2]);
      pack_h2(sf[2 * j2 + 1][2], sf[2 * j2 + 1][3], ph[j2][3], pl[j2][3]);
    }

    // ---- O += P V (16x128 per warp) ----
#pragma unroll
    for (int j2 = 0; j2 < 4; j2++) {
      uint32_t ka = vb_addr + (uint32_t)(j2 * 16) * ROWB;
#pragma unroll
      for (int f2 = 0; f2 < 8; f2++) {
        uint32_t bvh[4], bvl[4];
        uint32_t a = ka + f2 * 32;
        ldsm4t(bvh, VHI + a);
        ldsm4t(bvl, VLO + a);
        mma_f16(of[2 * f2], ph[j2], bvh);
        mma_f16(of[2 * f2], ph[j2], bvl);
        mma_f16(of[2 * f2], pl[j2], bvh);
        mma_f16(of[2 * f2 + 1], ph[j2], bvh + 2);
        mma_f16(of[2 * f2 + 1], ph[j2], bvl + 2);
        mma_f16(of[2 * f2 + 1], pl[j2], bvh + 2);
      }
    }
    __syncthreads();
  }

  // ---- write O / l ----
  float inv0 = 1.0f / l0, inv1 = 1.0f / l1;
  int r0 = lane >> 2, r1 = r0 + 8;
  int cbase = 2 * (lane & 3);
  size_t row0 = (size_t)(m0 + wm + r0) * DH;
  size_t row1 = (size_t)(m0 + wm + r1) * DH;
#pragma unroll
  for (int f = 0; f < 16; f++) {
    *(float2*)&out[row0 + 8 * f + cbase] =
        make_float2(of[f][0] * inv0, of[f][1] * inv0);
    *(float2*)&out[row1 + 8 * f + cbase] =
        make_float2(of[f][2] * inv1, of[f][3] * inv1);
  }
}

// ---------------------------------------------------------------------------
extern "C" void kernel_launch(void* const* d_in, const int* in_sizes, int n_in,
                              void* d_out, int out_size) {
  const float* x  = (const float*)d_in[0];
  const float* Wq = (const float*)d_in[1];
  const float* Wk = (const float*)d_in[2];
  const float* Wv = (const float*)d_in[3];
  float* out = (float*)d_out;

  qkv_proj_kernel<<<dim3(NTOK / 64, 3, 1), 256>>>(x, Wq, Wk, Wv);

  cudaFuncSetAttribute(flash_mma, cudaFuncAttributeMaxDynamicSharedMemorySize,
                       SMEM_FLASH);
  flash_mma<<<NTOK / 64, 128, SMEM_FLASH>>>(out);
}

// round 4
// speedup vs baseline: 4.3091x; 1.7457x over previous
#include <cuda_runtime.h>
#include <cuda_bf16.h>
#include <cuda_fp16.h>
#include <cstdint>

#define NTOK 8192
#define DIN  1024
#define DH   128
#define NSPLIT 2
#define KEYS_PER_SPLIT (NTOK / NSPLIT)

// Split operands produced by the projection kernel.
__device__ __nv_bfloat16 g_Qhi[NTOK * DH], g_Qlo[NTOK * DH]; // pre-scaled by (1/sqrt d)*log2 e
__device__ __nv_bfloat16 g_Khi[NTOK * DH], g_Klo[NTOK * DH];
__device__ __half        g_Vhi[NTOK * DH], g_Vlo[NTOK * DH];
// Split-KV partials.
__device__ float g_Opart[NSPLIT * NTOK * DH];
__device__ float g_Mpart[NSPLIT * NTOK];
__device__ float g_Lpart[NSPLIT * NTOK];

__device__ __forceinline__ uint32_t smem_u32(const void* p) {
  uint32_t a;
  asm("{ .reg .u64 t; cvta.to.shared.u64 t, %1; cvt.u32.u64 %0, t; }"
      : "=r"(a) : "l"(p));
  return a;
}
__device__ __forceinline__ float ex2f(float x) {
  float y; asm("ex2.approx.ftz.f32 %0, %1;" : "=f"(y) : "f"(x)); return y;
}
__device__ __forceinline__ void ldsm4(uint32_t* r, uint32_t addr) {
  asm volatile("ldmatrix.sync.aligned.m8n8.x4.shared.b16 {%0,%1,%2,%3}, [%4];"
               : "=r"(r[0]), "=r"(r[1]), "=r"(r[2]), "=r"(r[3]) : "r"(addr));
}
__device__ __forceinline__ void ldsm4t(uint32_t* r, uint32_t addr) {
  asm volatile("ldmatrix.sync.aligned.m8n8.x4.trans.shared.b16 {%0,%1,%2,%3}, [%4];"
               : "=r"(r[0]), "=r"(r[1]), "=r"(r[2]), "=r"(r[3]) : "r"(addr));
}
__device__ __forceinline__ void mma_bf16(float* d, const uint32_t* a,
                                         const uint32_t* b) {
  asm volatile(
      "mma.sync.aligned.m16n8k16.row.col.f32.bf16.bf16.f32 "
      "{%0,%1,%2,%3}, {%4,%5,%6,%7}, {%8,%9}, {%0,%1,%2,%3};"
      : "+f"(d[0]), "+f"(d[1]), "+f"(d[2]), "+f"(d[3])
      : "r"(a[0]), "r"(a[1]), "r"(a[2]), "r"(a[3]), "r"(b[0]), "r"(b[1]));
}
__device__ __forceinline__ void mma_f16(float* d, const uint32_t* a,
                                        const uint32_t* b) {
  asm volatile(
      "mma.sync.aligned.m16n8k16.row.col.f32.f16.f16.f32 "
      "{%0,%1,%2,%3}, {%4,%5,%6,%7}, {%8,%9}, {%0,%1,%2,%3};"
      : "+f"(d[0]), "+f"(d[1]), "+f"(d[2]), "+f"(d[3])
      : "r"(a[0]), "r"(a[1]), "r"(a[2]), "r"(a[3]), "r"(b[0]), "r"(b[1]));
}
__device__ __forceinline__ void pack_h2(float x, float y, uint32_t& hi,
                                        uint32_t& lo) {
  __half2 h = __floats2half2_rn(x, y);
  float2 b = __half22float2(h);
  __half2 l = __floats2half2_rn(x - b.x, y - b.y);
  hi = *(uint32_t*)&h;
  lo = *(uint32_t*)&l;
}

// ---------------------------------------------------------------------------
// Kernel 1: QKV projection on HMMA with bf16 hi/lo (3-product) compensation.
// BM=128 (8 warps x 16 rows), BN=128 (full head dim), BK=64 tiles of DIN.
// grid = (NTOK/128, 3).  Epilogue emits split bf16/fp16 Q/K/V directly.
// ---------------------------------------------------------------------------
#define XROW 144   // bytes per smem x row (64 bf16 + 8 pad halves)
#define WROW 272   // bytes per smem W row (128 bf16 + 8 pad halves)
#define PXHI 0
#define PXLO 18432            // 128*144
#define PWHI 36864
#define PWLO 54272            // +64*272
#define SMEM_PROJ 71680

__global__ __launch_bounds__(256, 2) void qkv_proj_mma(
    const float* __restrict__ x,
    const float* __restrict__ Wq,
    const float* __restrict__ Wk,
    const float* __restrict__ Wv) {
  extern __shared__ char smc[];
  const int tid = threadIdx.x;
  const int lane = tid & 31, warp = tid >> 5;
  const int wm = warp * 16;
  const int mb = blockIdx.x * 128;
  const uint32_t sb = smem_u32(smc);

  const float* W;
  if (blockIdx.y == 0)      W = Wq;
  else if (blockIdx.y == 1) W = Wk;
  else                      W = Wv;

  float acc[16][4];
#pragma unroll
  for (int f = 0; f < 16; f++)
#pragma unroll
    for (int e = 0; e < 4; e++) acc[f][e] = 0.f;

  const uint32_t ah_addr = sb + PXHI + (uint32_t)(wm + (lane & 15)) * XROW +
                           (lane >> 4) * 16;
  const uint32_t bh_addr = sb + PWHI +
                           (uint32_t)((lane & 7) + ((lane >> 3) & 1) * 8) * WROW +
                           ((lane >> 4) & 1) * 16;

  for (int k0 = 0; k0 < DIN; k0 += 64) {
    __syncthreads();
    // Stage x tile [128][64] fp32 -> bf16 hi/lo.
#pragma unroll
    for (int it = 0; it < 8; it++) {
      int idx = tid + it * 256;
      int r = idx >> 4, c4 = idx & 15;
      float4 v = *(const float4*)&x[(size_t)(mb + r) * DIN + k0 + c4 * 4];
      __nv_bfloat16 h0 = __float2bfloat16_rn(v.x), h1 = __float2bfloat16_rn(v.y);
      __nv_bfloat16 h2 = __float2bfloat16_rn(v.z), h3 = __float2bfloat16_rn(v.w);
      __nv_bfloat162 hh0 = __halves2bfloat162(h0, h1);
      __nv_bfloat162 hh1 = __halves2bfloat162(h2, h3);
      __nv_bfloat162 ll0 = __halves2bfloat162(
          __float2bfloat16_rn(v.x - __bfloat162float(h0)),
          __float2bfloat16_rn(v.y - __bfloat162float(h1)));
      __nv_bfloat162 ll1 = __halves2bfloat162(
          __float2bfloat16_rn(v.z - __bfloat162float(h2)),
          __float2bfloat16_rn(v.w - __bfloat162float(h3)));
      uint32_t d = r * XROW + c4 * 8;
      *(uint2*)(smc + PXHI + d) = make_uint2(*(uint32_t*)&hh0, *(uint32_t*)&hh1);
      *(uint2*)(smc + PXLO + d) = make_uint2(*(uint32_t*)&ll0, *(uint32_t*)&ll1);
    }
    // Stage W tile [64][128] fp32 -> bf16 hi/lo.
#pragma unroll
    for (int it = 0; it < 8; it++) {
      int idx = tid + it * 256;
      int r = idx >> 5, c4 = idx & 31;
      float4 v = *(const float4*)&W[(size_t)(k0 + r) * DH + c4 * 4];
      __nv_bfloat16 h0 = __float2bfloat16_rn(v.x), h1 = __float2bfloat16_rn(v.y);
      __nv_bfloat16 h2 = __float2bfloat16_rn(v.z), h3 = __float2bfloat16_rn(v.w);
      __nv_bfloat162 hh0 = __halves2bfloat162(h0, h1);
      __nv_bfloat162 hh1 = __halves2bfloat162(h2, h3);
      __nv_bfloat162 ll0 = __halves2bfloat162(
          __float2bfloat16_rn(v.x - __bfloat162float(h0)),
          __float2bfloat16_rn(v.y - __bfloat162float(h1)));
      __nv_bfloat162 ll1 = __halves2bfloat162(
          __float2bfloat16_rn(v.z - __bfloat162float(h2)),
          __float2bfloat16_rn(v.w - __bfloat162float(h3)));
      uint32_t d = r * WROW + c4 * 8;
      *(uint2*)(smc + PWHI + d) = make_uint2(*(uint32_t*)&hh0, *(uint32_t*)&hh1);
      *(uint2*)(smc + PWLO + d) = make_uint2(*(uint32_t*)&ll0, *(uint32_t*)&ll1);
    }
    __syncthreads();

#pragma unroll
    for (int j = 0; j < 4; j++) {
      uint32_t ah[4], al[4];
      ldsm4(ah, ah_addr + j * 32);
      ldsm4(al, ah_addr + (PXLO - PXHI) + j * 32);
#pragma unroll
      for (int f2 = 0; f2 < 8; f2++) {
        uint32_t bh[4], bl[4];
        uint32_t a = bh_addr + (uint32_t)(j * 16) * WROW + f2 * 32;
        ldsm4t(bh, a);
        ldsm4t(bl, a + (PWLO - PWHI));
        mma_bf16(acc[2 * f2], ah, bh);
        mma_bf16(acc[2 * f2 + 1], ah, bh + 2);
        mma_bf16(acc[2 * f2], ah, bl);
        mma_bf16(acc[2 * f2 + 1], ah, bl + 2);
        mma_bf16(acc[2 * f2], al, bh);
        mma_bf16(acc[2 * f2 + 1], al, bh + 2);
      }
    }
  }

  // Epilogue: emit split operands.
  const float QSCALE = 0.08838834764831845f * 1.4426950408889634f;
  int r0 = mb + wm + (lane >> 2), r1 = r0 + 8;
  int cb = 2 * (lane & 3);
#pragma unroll
  for (int f = 0; f < 16; f++) {
    int c = 8 * f + cb;
    float v0 = acc[f][0], v1 = acc[f][1], v2 = acc[f][2], v3 = acc[f][3];
    if (blockIdx.y == 0) { v0 *= QSCALE; v1 *= QSCALE; v2 *= QSCALE; v3 *= QSCALE; }
    if (blockIdx.y == 2) {
      __half h0 = __float2half_rn(v0), h1 = __float2half_rn(v1);
      __half h2 = __float2half_rn(v2), h3 = __float2half_rn(v3);
      *(__half2*)&g_Vhi[(size_t)r0 * DH + c] = __halves2half2(h0, h1);
      *(__half2*)&g_Vhi[(size_t)r1 * DH + c] = __halves2half2(h2, h3);
      *(__half2*)&g_Vlo[(size_t)r0 * DH + c] = __halves2half2(
          __float2half_rn(v0 - __half2float(h0)), __float2half_rn(v1 - __half2float(h1)));
      *(__half2*)&g_Vlo[(size_t)r1 * DH + c] = __halves2half2(
          __float2half_rn(v2 - __half2float(h2)), __float2half_rn(v3 - __half2float(h3)));
    } else {
      __nv_bfloat16 h0 = __float2bfloat16_rn(v0), h1 = __float2bfloat16_rn(v1);
      __nv_bfloat16 h2 = __float2bfloat16_rn(v2), h3 = __float2bfloat16_rn(v3);
      __nv_bfloat16* hi = blockIdx.y ? g_Khi : g_Qhi;
      __nv_bfloat16* lo = blockIdx.y ? g_Klo : g_Qlo;
      *(__nv_bfloat162*)&hi[(size_t)r0 * DH + c] = __halves2bfloat162(h0, h1);
      *(__nv_bfloat162*)&hi[(size_t)r1 * DH + c] = __halves2bfloat162(h2, h3);
      *(__nv_bfloat162*)&lo[(size_t)r0 * DH + c] = __halves2bfloat162(
          __float2bfloat16_rn(v0 - __bfloat162float(h0)),
          __float2bfloat16_rn(v1 - __bfloat162float(h1)));
      *(__nv_bfloat162*)&lo[(size_t)r1 * DH + c] = __halves2bfloat162(
          __float2bfloat16_rn(v2 - __bfloat162float(h2)),
          __float2bfloat16_rn(v3 - __bfloat162float(h3)));
    }
  }
}

// ---------------------------------------------------------------------------
// Kernel 2: flash attention, BM=128 (8 warps), BN=64, split-KV x2.
// grid = (64, 2).  Writes unnormalized O + (m, l) partials.
// ---------------------------------------------------------------------------
#define ROWB 272
#define KHI 0
#define KLO 17408
#define VHI 34816
#define VLO 52224
#define SMEM_FLASH (4 * 17408)

__global__ __launch_bounds__(256, 1) void flash_mma(int dummy) {
  extern __shared__ char smc[];
  const int tid = threadIdx.x;
  const int lane = tid & 31, warp = tid >> 5;
  const int wm = warp * 16;
  const int mb = blockIdx.x * 128;
  const int split = blockIdx.y;
  const uint32_t sb = smem_u32(smc);

  // --- Stage Q (hi rows 0-63 -> KHI, 64-127 -> KLO; lo -> VHI/VLO) ---
#pragma unroll
  for (int it = 0; it < 8; it++) {
    int idx = tid + it * 256;
    int r = idx >> 4, c = idx & 15;
    size_t g = (size_t)(mb + r) * DH + c * 8;
    uint32_t d = (r >> 6) * 17408 + (r & 63) * ROWB + c * 16;
    *(float4*)(smc + KHI + d) = *(const float4*)(g_Qhi + g);
    *(float4*)(smc + VHI + d) = *(const float4*)(g_Qlo + g);
  }
  __syncthreads();

  uint32_t qh[8][4], ql[8][4];
  {
    uint32_t aoff = (uint32_t)(wm >= 64 ? 17408 : 0) +
                    (uint32_t)((wm & 63) + (lane & 15)) * ROWB + (lane >> 4) * 16;
#pragma unroll
    for (int j = 0; j < 8; j++) {
      ldsm4(qh[j], sb + KHI + aoff + j * 32);
      ldsm4(ql[j], sb + VHI + aoff + j * 32);
    }
  }
  __syncthreads();

  float of[16][4];
#pragma unroll
  for (int f = 0; f < 16; f++)
#pragma unroll
    for (int e = 0; e < 4; e++) of[f][e] = 0.f;
  float mrow0 = -1e30f, mrow1 = -1e30f, l0 = 0.f, l1 = 0.f;

  const uint32_t sb_addr = sb + (uint32_t)((lane & 7) + ((lane >> 4) << 3)) * ROWB +
                           ((lane >> 3) & 1) * 16;
  const uint32_t vb_addr = sb + (uint32_t)((lane & 7) + (((lane >> 3) & 1) << 3)) * ROWB +
                           ((lane >> 4) & 1) * 16;

  for (int tile = 0; tile < KEYS_PER_SPLIT / 64; tile++) {
    const int n0 = split * KEYS_PER_SPLIT + tile * 64;
#pragma unroll
    for (int it = 0; it < 4; it++) {
      int idx = tid + it * 256;
      int r = idx >> 4, c = idx & 15;
      size_t g = (size_t)(n0 + r) * DH + c * 8;
      uint32_t d = r * ROWB + c * 16;
      *(float4*)(smc + KHI + d) = *(const float4*)(g_Khi + g);
      *(float4*)(smc + KLO + d) = *(const float4*)(g_Klo + g);
      *(float4*)(smc + VHI + d) = *(const float4*)(g_Vhi + g);
      *(float4*)(smc + VLO + d) = *(const float4*)(g_Vlo + g);
    }
    __syncthreads();

    // ---- S = Q K^T (16x64 per warp) ----
    float sf[8][4];
#pragma unroll
    for (int f = 0; f < 8; f++)
#pragma unroll
      for (int e = 0; e < 4; e++) sf[f][e] = 0.f;

#pragma unroll
    for (int j = 0; j < 8; j++) {
#pragma unroll
      for (int f2 = 0; f2 < 4; f2++) {
        uint32_t bh[4], bl[4];
        uint32_t a = sb_addr + (uint32_t)(f2 * 16) * ROWB + j * 32;
        ldsm4(bh, KHI + a);
        ldsm4(bl, KLO + a);
        mma_bf16(sf[2 * f2], qh[j], bh);
        mma_bf16(sf[2 * f2 + 1], qh[j], bh + 2);
        mma_bf16(sf[2 * f2], qh[j], bl);
        mma_bf16(sf[2 * f2 + 1], qh[j], bl + 2);
        mma_bf16(sf[2 * f2], ql[j], bh);
        mma_bf16(sf[2 * f2 + 1], ql[j], bh + 2);
      }
    }

    // ---- online softmax (base-2 logits) ----
    float mx0 = sf[0][0], mx1 = sf[0][2];
#pragma unroll
    for (int f = 0; f < 8; f++) {
      mx0 = fmaxf(mx0, fmaxf(sf[f][0], sf[f][1]));
      mx1 = fmaxf(mx1, fmaxf(sf[f][2], sf[f][3]));
    }
    mx0 = fmaxf(mx0, __shfl_xor_sync(0xffffffffu, mx0, 1));
    mx0 = fmaxf(mx0, __shfl_xor_sync(0xffffffffu, mx0, 2));
    mx1 = fmaxf(mx1, __shfl_xor_sync(0xffffffffu, mx1, 1));
    mx1 = fmaxf(mx1, __shfl_xor_sync(0xffffffffu, mx1, 2));

    float mn0 = fmaxf(mrow0, mx0), mn1 = fmaxf(mrow1, mx1);
    float a0 = ex2f(mrow0 - mn0), a1 = ex2f(mrow1 - mn1);
    mrow0 = mn0; mrow1 = mn1;

    float s0 = 0.f, s1 = 0.f;
#pragma unroll
    for (int f = 0; f < 8; f++) {
      sf[f][0] = ex2f(sf[f][0] - mn0);
      sf[f][1] = ex2f(sf[f][1] - mn0);
      sf[f][2] = ex2f(sf[f][2] - mn1);
      sf[f][3] = ex2f(sf[f][3] - mn1);
      s0 += sf[f][0] + sf[f][1];
      s1 += sf[f][2] + sf[f][3];
    }
    s0 += __shfl_xor_sync(0xffffffffu, s0, 1);
    s0 += __shfl_xor_sync(0xffffffffu, s0, 2);
    s1 += __shfl_xor_sync(0xffffffffu, s1, 1);
    s1 += __shfl_xor_sync(0xffffffffu, s1, 2);
    l0 = l0 * a0 + s0;
    l1 = l1 * a1 + s1;

#pragma unroll
    for (int f = 0; f < 16; f++) {
      of[f][0] *= a0;  of[f][1] *= a0;
      of[f][2] *= a1;  of[f][3] *= a1;
    }

    // ---- P -> fp16 hi/lo fragments ----
    uint32_t ph[4][4], pl[4][4];
#pragma unroll
    for (int j2 = 0; j2 < 4; j2++) {
      pack_h2(sf[2 * j2][0],     sf[2 * j2][1],     ph[j2][0], pl[j2][0]);
      pack_h2(sf[2 * j2][2],     sf[2 * j2][3],     ph[j2][1], pl[j2][1]);
      pack_h2(sf[2 * j2 + 1][0], sf[2 * j2 + 1][1], ph[j2][2], pl[j2][2]);
      pack_h2(sf[2 * j2 + 1][2], sf[2 * j2 + 1][3], ph[j2][3], pl[j2][3]);
    }

    // ---- O += P V ----
#pragma unroll
    for (int j2 = 0; j2 < 4; j2++) {
      uint32_t ka = vb_addr + (uint32_t)(j2 * 16) * ROWB;
#pragma unroll
      for (int f2 = 0; f2 < 8; f2++) {
        uint32_t bvh[4], bvl[4];
        uint32_t a = ka + f2 * 32;
        ldsm4t(bvh, VHI + a);
        ldsm4t(bvl, VLO + a);
        mma_f16(of[2 * f2], ph[j2], bvh);
        mma_f16(of[2 * f2 + 1], ph[j2], bvh + 2);
        mma_f16(of[2 * f2], ph[j2], bvl);
        mma_f16(of[2 * f2 + 1], ph[j2], bvl + 2);
        mma_f16(of[2 * f2], pl[j2], bvh);
        mma_f16(of[2 * f2 + 1], pl[j2], bvh + 2);
      }
    }
    __syncthreads();
  }

  // ---- write partials ----
  int r0 = lane >> 2, r1 = r0 + 8;
  int cbase = 2 * (lane & 3);
  size_t orow0 = (size_t)(split * NTOK + mb + wm + r0) * DH;
  size_t orow1 = (size_t)(split * NTOK + mb + wm + r1) * DH;
#pragma unroll
  for (int f = 0; f < 16; f++) {
    *(float2*)&g_Opart[orow0 + 8 * f + cbase] = make_float2(of[f][0], of[f][1]);
    *(float2*)&g_Opart[orow1 + 8 * f + cbase] = make_float2(of[f][2], of[f][3]);
  }
  if ((lane & 3) == 0) {
    g_Mpart[split * NTOK + mb + wm + r0] = mrow0;
    g_Lpart[split * NTOK + mb + wm + r0] = l0;
    g_Mpart[split * NTOK + mb + wm + r1] = mrow1;
    g_Lpart[split * NTOK + mb + wm + r1] = l1;
  }
}

// ---------------------------------------------------------------------------
// Kernel 3: split-KV merge.  8 rows per block, 32 threads/row (float4 cols).
// ---------------------------------------------------------------------------
__global__ __launch_bounds__(256) void merge_kernel(float* __restrict__ out) {
  const int tid = threadIdx.x;
  const int row = blockIdx.x * 8 + (tid >> 5);
  const int c4 = (tid & 31) * 4;

  float ma = g_Mpart[row], la = g_Lpart[row];
  float mb2 = g_Mpart[NTOK + row], lb = g_Lpart[NTOK + row];
  float M = fmaxf(ma, mb2);
  float wa = ex2f(ma - M), wb = ex2f(mb2 - M);
  float inv = 1.0f / (wa * la + wb * lb);

  float4 oa = *(const float4*)&g_Opart[(size_t)row * DH + c4];
  float4 ob = *(const float4*)&g_Opart[(size_t)(NTOK + row) * DH + c4];
  float4 r;
  r.x = (wa * oa.x + wb * ob.x) * inv;
  r.y = (wa * oa.y + wb * ob.y) * inv;
  r.z = (wa * oa.z + wb * ob.z) * inv;
  r.w = (wa * oa.w + wb * ob.w) * inv;
  *(float4*)&out[(size_t)row * DH + c4] = r;
}

// ---------------------------------------------------------------------------
extern "C" void kernel_launch(void* const* d_in, const int* in_sizes, int n_in,
                              void* d_out, int out_size) {
  const float* x  = (const float*)d_in[0];
  const float* Wq = (const float*)d_in[1];
  const float* Wk = (const float*)d_in[2];
  const float* Wv = (const float*)d_in[3];
  float* out = (float*)d_out;

  cudaFuncSetAttribute(qkv_proj_mma, cudaFuncAttributeMaxDynamicSharedMemorySize,
                       SMEM_PROJ);
  qkv_proj_mma<<<dim3(NTOK / 128, 3, 1), 256, SMEM_PROJ>>>(x, Wq, Wk, Wv);

  cudaFuncSetAttribute(flash_mma, cudaFuncAttributeMaxDynamicSharedMemorySize,
                       SMEM_FLASH);
  flash_mma<<<dim3(NTOK / 128, NSPLIT, 1), 256, SMEM_FLASH>>>(0);

  merge_kernel<<<NTOK / 8, 256>>>(out);
}

// round 5
// speedup vs baseline: 4.7250x; 1.0965x over previous
#include <cuda_runtime.h>
#include <cuda_bf16.h>
#include <cuda_fp16.h>
#include <cstdint>

#define NTOK 8192
#define DIN  1024
#define DH   128
#define NSPLIT 2
#define KEYS_PER_SPLIT (NTOK / NSPLIT)

// Pre-split inputs (prep kernels).
__device__ __nv_bfloat16 g_Xhi[NTOK * DIN], g_Xlo[NTOK * DIN];
__device__ __nv_bfloat16 g_Whi[3 * DIN * DH], g_Wlo[3 * DIN * DH];
// Split operands produced by the projection kernel.
__device__ __nv_bfloat16 g_Qhi[NTOK * DH], g_Qlo[NTOK * DH]; // pre-scaled by (1/sqrt d)*log2 e
__device__ __nv_bfloat16 g_Khi[NTOK * DH], g_Klo[NTOK * DH];
__device__ __half        g_Vhi[NTOK * DH], g_Vlo[NTOK * DH];
// Split-KV partials.
__device__ float g_Opart[NSPLIT * NTOK * DH];
__device__ float g_Mpart[NSPLIT * NTOK];
__device__ float g_Lpart[NSPLIT * NTOK];

__device__ __forceinline__ uint32_t smem_u32(const void* p) {
  uint32_t a;
  asm("{ .reg .u64 t; cvta.to.shared.u64 t, %1; cvt.u32.u64 %0, t; }"
      : "=r"(a) : "l"(p));
  return a;
}
__device__ __forceinline__ float ex2f(float x) {
  float y; asm("ex2.approx.ftz.f32 %0, %1;" : "=f"(y) : "f"(x)); return y;
}
__device__ __forceinline__ void ldsm4(uint32_t* r, uint32_t addr) {
  asm volatile("ldmatrix.sync.aligned.m8n8.x4.shared.b16 {%0,%1,%2,%3}, [%4];"
               : "=r"(r[0]), "=r"(r[1]), "=r"(r[2]), "=r"(r[3]) : "r"(addr));
}
__device__ __forceinline__ void ldsm4t(uint32_t* r, uint32_t addr) {
  asm volatile("ldmatrix.sync.aligned.m8n8.x4.trans.shared.b16 {%0,%1,%2,%3}, [%4];"
               : "=r"(r[0]), "=r"(r[1]), "=r"(r[2]), "=r"(r[3]) : "r"(addr));
}
__device__ __forceinline__ void mma_bf16(float* d, const uint32_t* a,
                                         const uint32_t* b) {
  asm volatile(
      "mma.sync.aligned.m16n8k16.row.col.f32.bf16.bf16.f32 "
      "{%0,%1,%2,%3}, {%4,%5,%6,%7}, {%8,%9}, {%0,%1,%2,%3};"
      : "+f"(d[0]), "+f"(d[1]), "+f"(d[2]), "+f"(d[3])
      : "r"(a[0]), "r"(a[1]), "r"(a[2]), "r"(a[3]), "r"(b[0]), "r"(b[1]));
}
__device__ __forceinline__ void mma_f16(float* d, const uint32_t* a,
                                        const uint32_t* b) {
  asm volatile(
      "mma.sync.aligned.m16n8k16.row.col.f32.f16.f16.f32 "
      "{%0,%1,%2,%3}, {%4,%5,%6,%7}, {%8,%9}, {%0,%1,%2,%3};"
      : "+f"(d[0]), "+f"(d[1]), "+f"(d[2]), "+f"(d[3])
      : "r"(a[0]), "r"(a[1]), "r"(a[2]), "r"(a[3]), "r"(b[0]), "r"(b[1]));
}
__device__ __forceinline__ void cpa16(uint32_t dst, const void* src) {
  asm volatile("cp.async.cg.shared.global [%0], [%1], 16;" :: "r"(dst), "l"(src));
}
#define CP_COMMIT() asm volatile("cp.async.commit_group;" ::: "memory")
#define CP_WAIT1() asm volatile("cp.async.wait_group 1;" ::: "memory")
#define CP_WAIT0() asm volatile("cp.async.wait_group 0;" ::: "memory")

// ---------------------------------------------------------------------------
// Prep kernels: split fp32 -> bf16 hi/lo.
// ---------------------------------------------------------------------------
__global__ __launch_bounds__(256) void split_x_kernel(const float* __restrict__ x) {
  size_t i = ((size_t)blockIdx.x * 256 + threadIdx.x) * 4;
  float4 v = *(const float4*)(x + i);
  __nv_bfloat16 h0 = __float2bfloat16_rn(v.x), h1 = __float2bfloat16_rn(v.y);
  __nv_bfloat16 h2 = __float2bfloat16_rn(v.z), h3 = __float2bfloat16_rn(v.w);
  __nv_bfloat162 hh0 = __halves2bfloat162(h0, h1), hh1 = __halves2bfloat162(h2, h3);
  __nv_bfloat162 ll0 = __halves2bfloat162(
      __float2bfloat16_rn(v.x - __bfloat162float(h0)),
      __float2bfloat16_rn(v.y - __bfloat162float(h1)));
  __nv_bfloat162 ll1 = __halves2bfloat162(
      __float2bfloat16_rn(v.z - __bfloat162float(h2)),
      __float2bfloat16_rn(v.w - __bfloat162float(h3)));
  *(uint2*)&g_Xhi[i] = make_uint2(*(uint32_t*)&hh0, *(uint32_t*)&hh1);
  *(uint2*)&g_Xlo[i] = make_uint2(*(uint32_t*)&ll0, *(uint32_t*)&ll1);
}

__global__ __launch_bounds__(256) void split_w_kernel(
    const float* __restrict__ Wq, const float* __restrict__ Wk,
    const float* __restrict__ Wv) {
  const float* W;
  float sc = 1.0f;
  if (blockIdx.y == 0) { W = Wq; sc = 0.08838834764831845f * 1.4426950408889634f; }
  else if (blockIdx.y == 1) W = Wk;
  else W = Wv;
  size_t i = ((size_t)blockIdx.x * 256 + threadIdx.x) * 4;
  float4 v = *(const float4*)(W + i);
  v.x *= sc; v.y *= sc; v.z *= sc; v.w *= sc;
  __nv_bfloat16 h0 = __float2bfloat16_rn(v.x), h1 = __float2bfloat16_rn(v.y);
  __nv_bfloat16 h2 = __float2bfloat16_rn(v.z), h3 = __float2bfloat16_rn(v.w);
  __nv_bfloat162 hh0 = __halves2bfloat162(h0, h1), hh1 = __halves2bfloat162(h2, h3);
  __nv_bfloat162 ll0 = __halves2bfloat162(
      __float2bfloat16_rn(v.x - __bfloat162float(h0)),
      __float2bfloat16_rn(v.y - __bfloat162float(h1)));
  __nv_bfloat162 ll1 = __halves2bfloat162(
      __float2bfloat16_rn(v.z - __bfloat162float(h2)),
      __float2bfloat16_rn(v.w - __bfloat162float(h3)));
  size_t o = (size_t)blockIdx.y * DIN * DH + i;
  *(uint2*)&g_Whi[o] = make_uint2(*(uint32_t*)&hh0, *(uint32_t*)&hh1);
  *(uint2*)&g_Wlo[o] = make_uint2(*(uint32_t*)&ll0, *(uint32_t*)&ll1);
}

// ---------------------------------------------------------------------------
// Kernel 1: QKV projection GEMM on pre-split bf16, cp.async double-buffered.
// BM=128, BN=128, BK=64.  grid = (NTOK/128, 3).
// Stage layout (bytes): XHI 0 (128x144), XLO 18432, WHI 36864 (64x272),
// WLO 54272; stage size 71680, two stages.
// ---------------------------------------------------------------------------
#define XROW 144
#define WROW 272
#define PSTAGE 71680
#define SMEM_PROJ (2 * PSTAGE)

__device__ __forceinline__ void proj_issue(int tid, int mb, int y, int k0,
                                           uint32_t dstbase) {
#pragma unroll
  for (int it = 0; it < 8; it++) {
    int idx = tid + it * 256;
    int arr = idx >> 10, w = idx & 1023;
    int r = w >> 3, c = w & 7;
    const __nv_bfloat16* src = (arr ? g_Xlo : g_Xhi) +
                               (size_t)(mb + r) * DIN + k0 + c * 8;
    cpa16(dstbase + arr * 18432 + r * XROW + c * 16, src);
  }
#pragma unroll
  for (int it = 0; it < 8; it++) {
    int idx = tid + it * 256;
    int arr = idx >> 10, w = idx & 1023;
    int r = w >> 4, c = w & 15;
    const __nv_bfloat16* src = (arr ? g_Wlo : g_Whi) +
                               (size_t)y * DIN * DH + (size_t)(k0 + r) * DH + c * 8;
    cpa16(dstbase + 36864 + arr * 17408 + r * WROW + c * 16, src);
  }
}

__global__ __launch_bounds__(256, 1) void qkv_proj_mma() {
  extern __shared__ char smc[];
  const int tid = threadIdx.x;
  const int lane = tid & 31, warp = tid >> 5;
  const int wm = warp * 16;
  const int mb = blockIdx.x * 128;
  const int y = blockIdx.y;
  const uint32_t sb = smem_u32(smc);

  float acc[16][4];
#pragma unroll
  for (int f = 0; f < 16; f++)
#pragma unroll
    for (int e = 0; e < 4; e++) acc[f][e] = 0.f;

  const uint32_t ah_addr = sb + (uint32_t)(wm + (lane & 15)) * XROW +
                           (lane >> 4) * 16;
  const uint32_t bh_addr = sb + 36864 +
                           (uint32_t)((lane & 7) + ((lane >> 3) & 1) * 8) * WROW +
                           ((lane >> 4) & 1) * 16;

  proj_issue(tid, mb, y, 0, sb);          CP_COMMIT();
  proj_issue(tid, mb, y, 64, sb + PSTAGE); CP_COMMIT();

  const int NT = DIN / 64;   // 16
  for (int t = 0; t < NT; t++) {
    if (t + 1 < NT) CP_WAIT1(); else CP_WAIT0();
    __syncthreads();
    uint32_t bo = (uint32_t)(t & 1) * PSTAGE;
#pragma unroll
    for (int j = 0; j < 4; j++) {
      uint32_t ah[4], al[4];
      ldsm4(ah, ah_addr + bo + j * 32);
      ldsm4(al, ah_addr + bo + 18432 + j * 32);
#pragma unroll
      for (int f2 = 0; f2 < 8; f2++) {
        uint32_t bh[4], bl[4];
        uint32_t a = bh_addr + bo + (uint32_t)(j * 16) * WROW + f2 * 32;
        ldsm4t(bh, a);
        ldsm4t(bl, a + 17408);
        mma_bf16(acc[2 * f2], ah, bh);
        mma_bf16(acc[2 * f2 + 1], ah, bh + 2);
        mma_bf16(acc[2 * f2], ah, bl);
        mma_bf16(acc[2 * f2 + 1], ah, bl + 2);
        mma_bf16(acc[2 * f2], al, bh);
        mma_bf16(acc[2 * f2 + 1], al, bh + 2);
      }
    }
    __syncthreads();
    if (t + 2 < NT) { proj_issue(tid, mb, y, (t + 2) * 64, sb + bo); }
    CP_COMMIT();
  }

  // Epilogue: emit split operands (Q pre-scaled via Wq split).
  int r0 = mb + wm + (lane >> 2), r1 = r0 + 8;
  int cb = 2 * (lane & 3);
#pragma unroll
  for (int f = 0; f < 16; f++) {
    int c = 8 * f + cb;
    float v0 = acc[f][0], v1 = acc[f][1], v2 = acc[f][2], v3 = acc[f][3];
    if (y == 2) {
      __half h0 = __float2half_rn(v0), h1 = __float2half_rn(v1);
      __half h2 = __float2half_rn(v2), h3 = __float2half_rn(v3);
      *(__half2*)&g_Vhi[(size_t)r0 * DH + c] = __halves2half2(h0, h1);
      *(__half2*)&g_Vhi[(size_t)r1 * DH + c] = __halves2half2(h2, h3);
      *(__half2*)&g_Vlo[(size_t)r0 * DH + c] = __halves2half2(
          __float2half_rn(v0 - __half2float(h0)), __float2half_rn(v1 - __half2float(h1)));
      *(__half2*)&g_Vlo[(size_t)r1 * DH + c] = __halves2half2(
          __float2half_rn(v2 - __half2float(h2)), __float2half_rn(v3 - __half2float(h3)));
    } else {
      __nv_bfloat16 h0 = __float2bfloat16_rn(v0), h1 = __float2bfloat16_rn(v1);
      __nv_bfloat16 h2 = __float2bfloat16_rn(v2), h3 = __float2bfloat16_rn(v3);
      __nv_bfloat16* hi = y ? g_Khi : g_Qhi;
      __nv_bfloat16* lo = y ? g_Klo : g_Qlo;
      *(__nv_bfloat162*)&hi[(size_t)r0 * DH + c] = __halves2bfloat162(h0, h1);
      *(__nv_bfloat162*)&hi[(size_t)r1 * DH + c] = __halves2bfloat162(h2, h3);
      *(__nv_bfloat162*)&lo[(size_t)r0 * DH + c] = __halves2bfloat162(
          __float2bfloat16_rn(v0 - __bfloat162float(h0)),
          __float2bfloat16_rn(v1 - __bfloat162float(h1)));
      *(__nv_bfloat162*)&lo[(size_t)r1 * DH + c] = __halves2bfloat162(
          __float2bfloat16_rn(v2 - __bfloat162float(h2)),
          __float2bfloat16_rn(v3 - __bfloat162float(h3)));
    }
  }
}

// ---------------------------------------------------------------------------
// Kernel 2: flash attention, BM=128 (8 warps), BN=64, split-KV x2,
// cp.async double-buffered K/V, PV with 2-product compensation.
// Buffer layout per stage: KHI 0, KLO 17408, VHI 34816, VLO 52224 (each
// 64 rows x 272B); stage size 69632, two stages.
// ---------------------------------------------------------------------------
#define ROWB 272
#define KHI 0
#define KLO 17408
#define VHI 34816
#define VLO 52224
#define FSTAGE 69632
#define SMEM_FLASH (2 * FSTAGE)

__device__ __forceinline__ void flash_issue(int tid, int n0, uint32_t dstbase) {
#pragma unroll
  for (int arr = 0; arr < 4; arr++) {
    const __nv_bfloat16* srcb;
    if (arr == 0)      srcb = g_Khi;
    else if (arr == 1) srcb = g_Klo;
    else if (arr == 2) srcb = (const __nv_bfloat16*)g_Vhi;
    else               srcb = (const __nv_bfloat16*)g_Vlo;
#pragma unroll
    for (int it = 0; it < 4; it++) {
      int idx = tid + it * 256;
      int r = idx >> 4, c = idx & 15;
      cpa16(dstbase + arr * 17408 + r * ROWB + c * 16,
            srcb + (size_t)(n0 + r) * DH + c * 8);
    }
  }
}

__global__ __launch_bounds__(256, 1) void flash_mma(int dummy) {
  extern __shared__ char smc[];
  const int tid = threadIdx.x;
  const int lane = tid & 31, warp = tid >> 5;
  const int wm = warp * 16;
  const int mb = blockIdx.x * 128;
  const int split = blockIdx.y;
  const int nbase = split * KEYS_PER_SPLIT;
  const uint32_t sb = smem_u32(smc);

  // Start loading tile 0 into stage-1 buffer immediately.
  flash_issue(tid, nbase, sb + FSTAGE);
  CP_COMMIT();

  // --- Stage Q into stage-0 buffer (hi -> KHI/KLO, lo -> VHI/VLO) ---
#pragma unroll
  for (int it = 0; it < 8; it++) {
    int idx = tid + it * 256;
    int r = idx >> 4, c = idx & 15;
    size_t g = (size_t)(mb + r) * DH + c * 8;
    uint32_t d = (r >> 6) * 17408 + (r & 63) * ROWB + c * 16;
    *(float4*)(smc + KHI + d) = *(const float4*)(g_Qhi + g);
    *(float4*)(smc + VHI + d) = *(const float4*)(g_Qlo + g);
  }
  __syncthreads();

  uint32_t qh[8][4], ql[8][4];
  {
    uint32_t aoff = (uint32_t)(wm >= 64 ? 17408 : 0) +
                    (uint32_t)((wm & 63) + (lane & 15)) * ROWB + (lane >> 4) * 16;
#pragma unroll
    for (int j = 0; j < 8; j++) {
      ldsm4(qh[j], sb + KHI + aoff + j * 32);
      ldsm4(ql[j], sb + VHI + aoff + j * 32);
    }
  }
  __syncthreads();

  // Tile 1 into stage-0 (Q regions now free).
  flash_issue(tid, nbase + 64, sb);
  CP_COMMIT();

  float of[16][4];
#pragma unroll
  for (int f = 0; f < 16; f++)
#pragma unroll
    for (int e = 0; e < 4; e++) of[f][e] = 0.f;
  float mrow0 = -1e30f, mrow1 = -1e30f, l0 = 0.f, l1 = 0.f;

  const uint32_t sb_addr = sb + (uint32_t)((lane & 7) + ((lane >> 4) << 3)) * ROWB +
                           ((lane >> 3) & 1) * 16;
  const uint32_t vb_addr = sb + (uint32_t)((lane & 7) + (((lane >> 3) & 1) << 3)) * ROWB +
                           ((lane >> 4) & 1) * 16;

  const int NT = KEYS_PER_SPLIT / 64;   // 64
  for (int tile = 0; tile < NT; tile++) {
    if (tile + 1 < NT) CP_WAIT1(); else CP_WAIT0();
    __syncthreads();
    const uint32_t bo = (uint32_t)((tile + 1) & 1) * FSTAGE;  // tile0->stage1

    // ---- S = Q K^T (16x64 per warp) ----
    float sf[8][4];
#pragma unroll
    for (int f = 0; f < 8; f++)
#pragma unroll
      for (int e = 0; e < 4; e++) sf[f][e] = 0.f;

#pragma unroll
    for (int j = 0; j < 8; j++) {
#pragma unroll
      for (int f2 = 0; f2 < 4; f2++) {
        uint32_t bh[4], bl[4];
        uint32_t a = sb_addr + bo + (uint32_t)(f2 * 16) * ROWB + j * 32;
        ldsm4(bh, KHI + a);
        ldsm4(bl, KLO + a);
        mma_bf16(sf[2 * f2], qh[j], bh);
        mma_bf16(sf[2 * f2 + 1], qh[j], bh + 2);
        mma_bf16(sf[2 * f2], qh[j], bl);
        mma_bf16(sf[2 * f2 + 1], qh[j], bl + 2);
        mma_bf16(sf[2 * f2], ql[j], bh);
        mma_bf16(sf[2 * f2 + 1], ql[j], bh + 2);
      }
    }

    // ---- online softmax (base-2 logits) ----
    float mx0 = sf[0][0], mx1 = sf[0][2];
#pragma unroll
    for (int f = 0; f < 8; f++) {
      mx0 = fmaxf(mx0, fmaxf(sf[f][0], sf[f][1]));
      mx1 = fmaxf(mx1, fmaxf(sf[f][2], sf[f][3]));
    }
    mx0 = fmaxf(mx0, __shfl_xor_sync(0xffffffffu, mx0, 1));
    mx0 = fmaxf(mx0, __shfl_xor_sync(0xffffffffu, mx0, 2));
    mx1 = fmaxf(mx1, __shfl_xor_sync(0xffffffffu, mx1, 1));
    mx1 = fmaxf(mx1, __shfl_xor_sync(0xffffffffu, mx1, 2));

    float mn0 = fmaxf(mrow0, mx0), mn1 = fmaxf(mrow1, mx1);
    float a0 = ex2f(mrow0 - mn0), a1 = ex2f(mrow1 - mn1);
    mrow0 = mn0; mrow1 = mn1;

    float s0 = 0.f, s1 = 0.f;
#pragma unroll
    for (int f = 0; f < 8; f++) {
      sf[f][0] = ex2f(sf[f][0] - mn0);
      sf[f][1] = ex2f(sf[f][1] - mn0);
      sf[f][2] = ex2f(sf[f][2] - mn1);
      sf[f][3] = ex2f(sf[f][3] - mn1);
      s0 += sf[f][0] + sf[f][1];
      s1 += sf[f][2] + sf[f][3];
    }
    s0 += __shfl_xor_sync(0xffffffffu, s0, 1);
    s0 += __shfl_xor_sync(0xffffffffu, s0, 2);
    s1 += __shfl_xor_sync(0xffffffffu, s1, 1);
    s1 += __shfl_xor_sync(0xffffffffu, s1, 2);
    l0 = l0 * a0 + s0;
    l1 = l1 * a1 + s1;

#pragma unroll
    for (int f = 0; f < 16; f++) {
      of[f][0] *= a0;  of[f][1] *= a0;
      of[f][2] *= a1;  of[f][3] *= a1;
    }

    // ---- P -> fp16 fragments (hi only; 2-product PV) ----
    uint32_t ph[4][4];
#pragma unroll
    for (int j2 = 0; j2 < 4; j2++) {
      __half2 h;
      h = __floats2half2_rn(sf[2 * j2][0], sf[2 * j2][1]);     ph[j2][0] = *(uint32_t*)&h;
      h = __floats2half2_rn(sf[2 * j2][2], sf[2 * j2][3]);     ph[j2][1] = *(uint32_t*)&h;
      h = __floats2half2_rn(sf[2 * j2 + 1][0], sf[2 * j2 + 1][1]); ph[j2][2] = *(uint32_t*)&h;
      h = __floats2half2_rn(sf[2 * j2 + 1][2], sf[2 * j2 + 1][3]); ph[j2][3] = *(uint32_t*)&h;
    }

    // ---- O += P V (Phi*Vhi + Phi*Vlo) ----
#pragma unroll
    for (int j2 = 0; j2 < 4; j2++) {
      uint32_t ka = vb_addr + bo + (uint32_t)(j2 * 16) * ROWB;
#pragma unroll
      for (int f2 = 0; f2 < 8; f2++) {
        uint32_t bvh[4], bvl[4];
        uint32_t a = ka + f2 * 32;
        ldsm4t(bvh, VHI + a);
        ldsm4t(bvl, VLO + a);
        mma_f16(of[2 * f2], ph[j2], bvh);
        mma_f16(of[2 * f2 + 1], ph[j2], bvh + 2);
        mma_f16(of[2 * f2], ph[j2], bvl);
        mma_f16(of[2 * f2 + 1], ph[j2], bvl + 2);
      }
    }
    __syncthreads();
    if (tile + 2 < NT) { flash_issue(tid, nbase + (tile + 2) * 64, sb + bo); }
    CP_COMMIT();
  }

  // ---- write partials ----
  int r0 = lane >> 2, r1 = r0 + 8;
  int cbase = 2 * (lane & 3);
  size_t orow0 = (size_t)(split * NTOK + mb + wm + r0) * DH;
  size_t orow1 = (size_t)(split * NTOK + mb + wm + r1) * DH;
#pragma unroll
  for (int f = 0; f < 16; f++) {
    *(float2*)&g_Opart[orow0 + 8 * f + cbase] = make_float2(of[f][0], of[f][1]);
    *(float2*)&g_Opart[orow1 + 8 * f + cbase] = make_float2(of[f][2], of[f][3]);
  }
  if ((lane & 3) == 0) {
    g_Mpart[split * NTOK + mb + wm + r0] = mrow0;
    g_Lpart[split * NTOK + mb + wm + r0] = l0;
    g_Mpart[split * NTOK + mb + wm + r1] = mrow1;
    g_Lpart[split * NTOK + mb + wm + r1] = l1;
  }
}

// ---------------------------------------------------------------------------
// Kernel 3: split-KV merge.
// ---------------------------------------------------------------------------
__global__ __launch_bounds__(256) void merge_kernel(float* __restrict__ out) {
  const int tid = threadIdx.x;
  const int row = blockIdx.x * 8 + (tid >> 5);
  const int c4 = (tid & 31) * 4;

  float ma = g_Mpart[row], la = g_Lpart[row];
  float mb2 = g_Mpart[NTOK + row], lb = g_Lpart[NTOK + row];
  float M = fmaxf(ma, mb2);
  float wa = ex2f(ma - M), wb = ex2f(mb2 - M);
  float inv = 1.0f / (wa * la + wb * lb);

  float4 oa = *(const float4*)&g_Opart[(size_t)row * DH + c4];
  float4 ob = *(const float4*)&g_Opart[(size_t)(NTOK + row) * DH + c4];
  float4 r;
  r.x = (wa * oa.x + wb * ob.x) * inv;
  r.y = (wa * oa.y + wb * ob.y) * inv;
  r.z = (wa * oa.z + wb * ob.z) * inv;
  r.w = (wa * oa.w + wb * ob.w) * inv;
  *(float4*)&out[(size_t)row * DH + c4] = r;
}

// ---------------------------------------------------------------------------
extern "C" void kernel_launch(void* const* d_in, const int* in_sizes, int n_in,
                              void* d_out, int out_size) {
  const float* x  = (const float*)d_in[0];
  const float* Wq = (const float*)d_in[1];
  const float* Wk = (const float*)d_in[2];
  const float* Wv = (const float*)d_in[3];
  float* out = (float*)d_out;

  split_x_kernel<<<NTOK * DIN / 1024, 256>>>(x);
  split_w_kernel<<<dim3(DIN * DH / 1024, 3, 1), 256>>>(Wq, Wk, Wv);

  cudaFuncSetAttribute(qkv_proj_mma, cudaFuncAttributeMaxDynamicSharedMemorySize,
                       SMEM_PROJ);
  qkv_proj_mma<<<dim3(NTOK / 128, 3, 1), 256, SMEM_PROJ>>>();

  cudaFuncSetAttribute(flash_mma, cudaFuncAttributeMaxDynamicSharedMemorySize,
                       SMEM_FLASH);
  flash_mma<<<dim3(NTOK / 128, NSPLIT, 1), 256, SMEM_FLASH>>>(0);

  merge_kernel<<<NTOK / 8, 256>>>(out);
}

// round 6
// speedup vs baseline: 5.3994x; 1.1427x over previous
#include <cuda_runtime.h>
#include <cuda_bf16.h>
#include <cuda_fp16.h>
#include <cstdint>

#define NTOK 8192
#define DIN  1024
#define DH   128
#define NSPLIT 2
#define KEYS_PER_SPLIT (NTOK / NSPLIT)

// Pre-split inputs (prep kernels).
__device__ __nv_bfloat16 g_Xhi[NTOK * DIN], g_Xlo[NTOK * DIN];
__device__ __nv_bfloat16 g_Whi[3 * DIN * DH], g_Wlo[3 * DIN * DH];
// Split operands produced by the projection kernel.
__device__ __nv_bfloat16 g_Qhi[NTOK * DH], g_Qlo[NTOK * DH]; // pre-scaled by (1/sqrt d)*log2 e
__device__ __nv_bfloat16 g_Khi[NTOK * DH], g_Klo[NTOK * DH];
__device__ __half        g_Vhi[NTOK * DH];
// Split-KV partials.
__device__ float g_Opart[NSPLIT * NTOK * DH];
__device__ float g_Mpart[NSPLIT * NTOK];
__device__ float g_Lpart[NSPLIT * NTOK];

__device__ __forceinline__ uint32_t smem_u32(const void* p) {
  uint32_t a;
  asm("{ .reg .u64 t; cvta.to.shared.u64 t, %1; cvt.u32.u64 %0, t; }"
      : "=r"(a) : "l"(p));
  return a;
}
__device__ __forceinline__ float ex2f(float x) {
  float y; asm("ex2.approx.ftz.f32 %0, %1;" : "=f"(y) : "f"(x)); return y;
}
__device__ __forceinline__ void ldsm4(uint32_t* r, uint32_t addr) {
  asm volatile("ldmatrix.sync.aligned.m8n8.x4.shared.b16 {%0,%1,%2,%3}, [%4];"
               : "=r"(r[0]), "=r"(r[1]), "=r"(r[2]), "=r"(r[3]) : "r"(addr));
}
__device__ __forceinline__ void ldsm4t(uint32_t* r, uint32_t addr) {
  asm volatile("ldmatrix.sync.aligned.m8n8.x4.trans.shared.b16 {%0,%1,%2,%3}, [%4];"
               : "=r"(r[0]), "=r"(r[1]), "=r"(r[2]), "=r"(r[3]) : "r"(addr));
}
__device__ __forceinline__ void mma_bf16(float* d, const uint32_t* a,
                                         const uint32_t* b) {
  asm volatile(
      "mma.sync.aligned.m16n8k16.row.col.f32.bf16.bf16.f32 "
      "{%0,%1,%2,%3}, {%4,%5,%6,%7}, {%8,%9}, {%0,%1,%2,%3};"
      : "+f"(d[0]), "+f"(d[1]), "+f"(d[2]), "+f"(d[3])
      : "r"(a[0]), "r"(a[1]), "r"(a[2]), "r"(a[3]), "r"(b[0]), "r"(b[1]));
}
__device__ __forceinline__ void mma_f16(float* d, const uint32_t* a,
                                        const uint32_t* b) {
  asm volatile(
      "mma.sync.aligned.m16n8k16.row.col.f32.f16.f16.f32 "
      "{%0,%1,%2,%3}, {%4,%5,%6,%7}, {%8,%9}, {%0,%1,%2,%3};"
      : "+f"(d[0]), "+f"(d[1]), "+f"(d[2]), "+f"(d[3])
      : "r"(a[0]), "r"(a[1]), "r"(a[2]), "r"(a[3]), "r"(b[0]), "r"(b[1]));
}
__device__ __forceinline__ void cpa16(uint32_t dst, const void* src) {
  asm volatile("cp.async.cg.shared.global [%0], [%1], 16;" :: "r"(dst), "l"(src));
}
#define CP_COMMIT() asm volatile("cp.async.commit_group;" ::: "memory")
#define CP_WAIT2() asm volatile("cp.async.wait_group 2;" ::: "memory")
#define CP_WAIT1() asm volatile("cp.async.wait_group 1;" ::: "memory")
#define CP_WAIT0() asm volatile("cp.async.wait_group 0;" ::: "memory")

// ---------------------------------------------------------------------------
// Prep kernels: split fp32 -> bf16 hi/lo.
// ---------------------------------------------------------------------------
__global__ __launch_bounds__(256) void split_x_kernel(const float* __restrict__ x) {
  size_t i = ((size_t)blockIdx.x * 256 + threadIdx.x) * 4;
  float4 v = *(const float4*)(x + i);
  __nv_bfloat16 h0 = __float2bfloat16_rn(v.x), h1 = __float2bfloat16_rn(v.y);
  __nv_bfloat16 h2 = __float2bfloat16_rn(v.z), h3 = __float2bfloat16_rn(v.w);
  __nv_bfloat162 hh0 = __halves2bfloat162(h0, h1), hh1 = __halves2bfloat162(h2, h3);
  __nv_bfloat162 ll0 = __halves2bfloat162(
      __float2bfloat16_rn(v.x - __bfloat162float(h0)),
      __float2bfloat16_rn(v.y - __bfloat162float(h1)));
  __nv_bfloat162 ll1 = __halves2bfloat162(
      __float2bfloat16_rn(v.z - __bfloat162float(h2)),
      __float2bfloat16_rn(v.w - __bfloat162float(h3)));
  *(uint2*)&g_Xhi[i] = make_uint2(*(uint32_t*)&hh0, *(uint32_t*)&hh1);
  *(uint2*)&g_Xlo[i] = make_uint2(*(uint32_t*)&ll0, *(uint32_t*)&ll1);
}

__global__ __launch_bounds__(256) void split_w_kernel(
    const float* __restrict__ Wq, const float* __restrict__ Wk,
    const float* __restrict__ Wv) {
  const float* W;
  float sc = 1.0f;
  if (blockIdx.y == 0) { W = Wq; sc = 0.08838834764831845f * 1.4426950408889634f; }
  else if (blockIdx.y == 1) W = Wk;
  else W = Wv;
  size_t i = ((size_t)blockIdx.x * 256 + threadIdx.x) * 4;
  float4 v = *(const float4*)(W + i);
  v.x *= sc; v.y *= sc; v.z *= sc; v.w *= sc;
  __nv_bfloat16 h0 = __float2bfloat16_rn(v.x), h1 = __float2bfloat16_rn(v.y);
  __nv_bfloat16 h2 = __float2bfloat16_rn(v.z), h3 = __float2bfloat16_rn(v.w);
  __nv_bfloat162 hh0 = __halves2bfloat162(h0, h1), hh1 = __halves2bfloat162(h2, h3);
  __nv_bfloat162 ll0 = __halves2bfloat162(
      __float2bfloat16_rn(v.x - __bfloat162float(h0)),
      __float2bfloat16_rn(v.y - __bfloat162float(h1)));
  __nv_bfloat162 ll1 = __halves2bfloat162(
      __float2bfloat16_rn(v.z - __bfloat162float(h2)),
      __float2bfloat16_rn(v.w - __bfloat162float(h3)));
  size_t o = (size_t)blockIdx.y * DIN * DH + i;
  *(uint2*)&g_Whi[o] = make_uint2(*(uint32_t*)&hh0, *(uint32_t*)&hh1);
  *(uint2*)&g_Wlo[o] = make_uint2(*(uint32_t*)&ll0, *(uint32_t*)&ll1);
}

// ---------------------------------------------------------------------------
// Kernel 1: QKV projection GEMM on pre-split bf16, cp.async double-buffered.
// ---------------------------------------------------------------------------
#define XROW 144
#define WROW 272
#define PSTAGE 71680
#define SMEM_PROJ (2 * PSTAGE)

__device__ __forceinline__ void proj_issue(int tid, int mb, int y, int k0,
                                           uint32_t dstbase) {
#pragma unroll
  for (int it = 0; it < 8; it++) {
    int idx = tid + it * 256;
    int arr = idx >> 10, w = idx & 1023;
    int r = w >> 3, c = w & 7;
    const __nv_bfloat16* src = (arr ? g_Xlo : g_Xhi) +
                               (size_t)(mb + r) * DIN + k0 + c * 8;
    cpa16(dstbase + arr * 18432 + r * XROW + c * 16, src);
  }
#pragma unroll
  for (int it = 0; it < 8; it++) {
    int idx = tid + it * 256;
    int arr = idx >> 10, w = idx & 1023;
    int r = w >> 4, c = w & 15;
    const __nv_bfloat16* src = (arr ? g_Wlo : g_Whi) +
                               (size_t)y * DIN * DH + (size_t)(k0 + r) * DH + c * 8;
    cpa16(dstbase + 36864 + arr * 17408 + r * WROW + c * 16, src);
  }
}

__global__ __launch_bounds__(256, 1) void qkv_proj_mma() {
  extern __shared__ char smc[];
  const int tid = threadIdx.x;
  const int lane = tid & 31, warp = tid >> 5;
  const int wm = warp * 16;
  const int mb = blockIdx.x * 128;
  const int y = blockIdx.y;
  const uint32_t sb = smem_u32(smc);

  float acc[16][4];
#pragma unroll
  for (int f = 0; f < 16; f++)
#pragma unroll
    for (int e = 0; e < 4; e++) acc[f][e] = 0.f;

  const uint32_t ah_addr = sb + (uint32_t)(wm + (lane & 15)) * XROW +
                           (lane >> 4) * 16;
  const uint32_t bh_addr = sb + 36864 +
                           (uint32_t)((lane & 7) + ((lane >> 3) & 1) * 8) * WROW +
                           ((lane >> 4) & 1) * 16;

  proj_issue(tid, mb, y, 0, sb);          CP_COMMIT();
  proj_issue(tid, mb, y, 64, sb + PSTAGE); CP_COMMIT();

  const int NT = DIN / 64;   // 16
  for (int t = 0; t < NT; t++) {
    if (t + 1 < NT) CP_WAIT1(); else CP_WAIT0();
    __syncthreads();
    uint32_t bo = (uint32_t)(t & 1) * PSTAGE;
#pragma unroll
    for (int j = 0; j < 4; j++) {
      uint32_t ah[4], al[4];
      ldsm4(ah, ah_addr + bo + j * 32);
      ldsm4(al, ah_addr + bo + 18432 + j * 32);
#pragma unroll
      for (int f2 = 0; f2 < 8; f2++) {
        uint32_t bh[4], bl[4];
        uint32_t a = bh_addr + bo + (uint32_t)(j * 16) * WROW + f2 * 32;
        ldsm4t(bh, a);
        ldsm4t(bl, a + 17408);
        mma_bf16(acc[2 * f2], ah, bh);
        mma_bf16(acc[2 * f2 + 1], ah, bh + 2);
        mma_bf16(acc[2 * f2], ah, bl);
        mma_bf16(acc[2 * f2 + 1], ah, bl + 2);
        mma_bf16(acc[2 * f2], al, bh);
        mma_bf16(acc[2 * f2 + 1], al, bh + 2);
      }
    }
    __syncthreads();
    if (t + 2 < NT) { proj_issue(tid, mb, y, (t + 2) * 64, sb + bo); }
    CP_COMMIT();
  }

  // Epilogue: emit split operands (Q pre-scaled via Wq split; V fp16 hi only).
  int r0 = mb + wm + (lane >> 2), r1 = r0 + 8;
  int cb = 2 * (lane & 3);
#pragma unroll
  for (int f = 0; f < 16; f++) {
    int c = 8 * f + cb;
    float v0 = acc[f][0], v1 = acc[f][1], v2 = acc[f][2], v3 = acc[f][3];
    if (y == 2) {
      *(__half2*)&g_Vhi[(size_t)r0 * DH + c] = __floats2half2_rn(v0, v1);
      *(__half2*)&g_Vhi[(size_t)r1 * DH + c] = __floats2half2_rn(v2, v3);
    } else {
      __nv_bfloat16 h0 = __float2bfloat16_rn(v0), h1 = __float2bfloat16_rn(v1);
      __nv_bfloat16 h2 = __float2bfloat16_rn(v2), h3 = __float2bfloat16_rn(v3);
      __nv_bfloat16* hi = y ? g_Khi : g_Qhi;
      __nv_bfloat16* lo = y ? g_Klo : g_Qlo;
      *(__nv_bfloat162*)&hi[(size_t)r0 * DH + c] = __halves2bfloat162(h0, h1);
      *(__nv_bfloat162*)&hi[(size_t)r1 * DH + c] = __halves2bfloat162(h2, h3);
      *(__nv_bfloat162*)&lo[(size_t)r0 * DH + c] = __halves2bfloat162(
          __float2bfloat16_rn(v0 - __bfloat162float(h0)),
          __float2bfloat16_rn(v1 - __bfloat162float(h1)));
      *(__nv_bfloat162*)&lo[(size_t)r1 * DH + c] = __halves2bfloat162(
          __float2bfloat16_rn(v2 - __bfloat162float(h2)),
          __float2bfloat16_rn(v3 - __bfloat162float(h3)));
    }
  }
}

// ---------------------------------------------------------------------------
// Kernel 2: flash attention, BM=128 (8 warps), BN=64, split-KV x2.
// 4-stage cp.async ring; S(t+1) MMAs fused into softmax(t)+PV(t) block so
// ptxas overlaps softmax ALU/MUFU with tensor work.  PV = Phi * Vhi (fp16).
// Stage: KHI 0, KLO 17408, VHI 34816; stage size 52224; 4 stages = 208896 B.
// ---------------------------------------------------------------------------
#define ROWB 272
#define SKLO 17408
#define SVHI 34816
#define FSTAGE 52224
#define SMEM_FLASH (4 * FSTAGE)
#define FNT (KEYS_PER_SPLIT / 64)   // 64 tiles

__device__ __forceinline__ void flash_issue(int tid, int n0, uint32_t dstbase) {
#pragma unroll
  for (int arr = 0; arr < 3; arr++) {
    const __nv_bfloat16* srcb;
    if (arr == 0)      srcb = g_Khi;
    else if (arr == 1) srcb = g_Klo;
    else               srcb = (const __nv_bfloat16*)g_Vhi;
#pragma unroll
    for (int it = 0; it < 4; it++) {
      int idx = tid + it * 256;
      int r = idx >> 4, c = idx & 15;
      cpa16(dstbase + arr * 17408 + r * ROWB + c * 16,
            srcb + (size_t)(n0 + r) * DH + c * 8);
    }
  }
}

// S = Q K^T for one key tile into sf (192 MMAs).
__device__ __forceinline__ void s_mma_tile(float sf[8][4], uint32_t kbase,
                                           const uint32_t qh[8][4],
                                           const uint32_t ql[8][4]) {
#pragma unroll
  for (int f = 0; f < 8; f++)
#pragma unroll
    for (int e = 0; e < 4; e++) sf[f][e] = 0.f;
#pragma unroll
  for (int j = 0; j < 8; j++) {
#pragma unroll
    for (int f2 = 0; f2 < 4; f2++) {
      uint32_t bh[4], bl[4];
      uint32_t a = kbase + (uint32_t)(f2 * 16) * ROWB + j * 32;
      ldsm4(bh, a);
      ldsm4(bl, a + SKLO);
      mma_bf16(sf[2 * f2], qh[j], bh);
      mma_bf16(sf[2 * f2 + 1], qh[j], bh + 2);
      mma_bf16(sf[2 * f2], qh[j], bl);
      mma_bf16(sf[2 * f2 + 1], qh[j], bl + 2);
      mma_bf16(sf[2 * f2], ql[j], bh);
      mma_bf16(sf[2 * f2 + 1], ql[j], bh + 2);
    }
  }
}

// Online softmax on sf (base-2 logits) + O rescale + PV accumulate.
__device__ __forceinline__ void softmax_pv(float sf[8][4], float of[16][4],
                                           float& mrow0, float& mrow1,
                                           float& l0, float& l1,
                                           uint32_t vbase) {
  float mx0 = sf[0][0], mx1 = sf[0][2];
#pragma unroll
  for (int f = 0; f < 8; f++) {
    mx0 = fmaxf(mx0, fmaxf(sf[f][0], sf[f][1]));
    mx1 = fmaxf(mx1, fmaxf(sf[f][2], sf[f][3]));
  }
  mx0 = fmaxf(mx0, __shfl_xor_sync(0xffffffffu, mx0, 1));
  mx0 = fmaxf(mx0, __shfl_xor_sync(0xffffffffu, mx0, 2));
  mx1 = fmaxf(mx1, __shfl_xor_sync(0xffffffffu, mx1, 1));
  mx1 = fmaxf(mx1, __shfl_xor_sync(0xffffffffu, mx1, 2));

  float mn0 = fmaxf(mrow0, mx0), mn1 = fmaxf(mrow1, mx1);
  float a0 = ex2f(mrow0 - mn0), a1 = ex2f(mrow1 - mn1);
  mrow0 = mn0; mrow1 = mn1;

  float s0 = 0.f, s1 = 0.f;
#pragma unroll
  for (int f = 0; f < 8; f++) {
    sf[f][0] = ex2f(sf[f][0] - mn0);
    sf[f][1] = ex2f(sf[f][1] - mn0);
    sf[f][2] = ex2f(sf[f][2] - mn1);
    sf[f][3] = ex2f(sf[f][3] - mn1);
    s0 += sf[f][0] + sf[f][1];
    s1 += sf[f][2] + sf[f][3];
  }
  s0 += __shfl_xor_sync(0xffffffffu, s0, 1);
  s0 += __shfl_xor_sync(0xffffffffu, s0, 2);
  s1 += __shfl_xor_sync(0xffffffffu, s1, 1);
  s1 += __shfl_xor_sync(0xffffffffu, s1, 2);
  l0 = l0 * a0 + s0;
  l1 = l1 * a1 + s1;

#pragma unroll
  for (int f = 0; f < 16; f++) {
    of[f][0] *= a0;  of[f][1] *= a0;
    of[f][2] *= a1;  of[f][3] *= a1;
  }

#pragma unroll
  for (int j2 = 0; j2 < 4; j2++) {
    uint32_t ph[4];
    __half2 h;
    h = __floats2half2_rn(sf[2 * j2][0], sf[2 * j2][1]);         ph[0] = *(uint32_t*)&h;
    h = __floats2half2_rn(sf[2 * j2][2], sf[2 * j2][3]);         ph[1] = *(uint32_t*)&h;
    h = __floats2half2_rn(sf[2 * j2 + 1][0], sf[2 * j2 + 1][1]); ph[2] = *(uint32_t*)&h;
    h = __floats2half2_rn(sf[2 * j2 + 1][2], sf[2 * j2 + 1][3]); ph[3] = *(uint32_t*)&h;
    uint32_t ka = vbase + (uint32_t)(j2 * 16) * ROWB;
#pragma unroll
    for (int f2 = 0; f2 < 8; f2++) {
      uint32_t bv[4];
      ldsm4t(bv, ka + f2 * 32);
      mma_f16(of[2 * f2], ph, bv);
      mma_f16(of[2 * f2 + 1], ph, bv + 2);
    }
  }
}

__global__ __launch_bounds__(256, 1) void flash_mma(int dummy) {
  extern __shared__ char smc[];
  const int tid = threadIdx.x;
  const int lane = tid & 31, warp = tid >> 5;
  const int wm = warp * 16;
  const int mb = blockIdx.x * 128;
  const int split = blockIdx.y;
  const int nbase = split * KEYS_PER_SPLIT;
  const uint32_t sb = smem_u32(smc);

  // Prefetch tiles 0 and 1 (stages 0/1 untouched by Q staging).
  flash_issue(tid, nbase, sb);                 CP_COMMIT();   // group 0
  flash_issue(tid, nbase + 64, sb + FSTAGE);   CP_COMMIT();   // group 1

  // Stage Q: Qhi -> stage3 [0,34816); Qlo rows 0-63 -> stage3+34816,
  // rows 64-127 -> stage2+34816 (stage2 not loaded until group 2 is issued).
  const uint32_t st2 = sb + 2 * FSTAGE, st3 = sb + 3 * FSTAGE;
#pragma unroll
  for (int it = 0; it < 8; it++) {
    int idx = tid + it * 256;
    int r = idx >> 4, c = idx & 15;
    size_t g = (size_t)(mb + r) * DH + c * 8;
    *(float4*)(smc + 3 * FSTAGE + r * ROWB + c * 16) = *(const float4*)(g_Qhi + g);
    uint32_t qlo_base = (r < 64 ? 3u : 2u) * FSTAGE + SVHI;
    *(float4*)(smc + qlo_base + (r & 63) * ROWB + c * 16) = *(const float4*)(g_Qlo + g);
  }
  __syncthreads();

  uint32_t qh[8][4], ql[8][4];
  {
    uint32_t hoff = st3 + (uint32_t)(wm + (lane & 15)) * ROWB + (lane >> 4) * 16;
    uint32_t loff = (wm < 64 ? st3 : st2) + SVHI +
                    (uint32_t)((wm & 63) + (lane & 15)) * ROWB + (lane >> 4) * 16;
#pragma unroll
    for (int j = 0; j < 8; j++) {
      ldsm4(qh[j], hoff + j * 32);
      ldsm4(ql[j], loff + j * 32);
    }
  }
  __syncthreads();   // Q areas dead; safe to load tile 2 into stage 2.
  flash_issue(tid, nbase + 128, st2);          CP_COMMIT();   // group 2

  float of[16][4];
#pragma unroll
  for (int f = 0; f < 16; f++)
#pragma unroll
    for (int e = 0; e < 4; e++) of[f][e] = 0.f;
  float mrow0 = -1e30f, mrow1 = -1e30f, l0 = 0.f, l1 = 0.f;
  float sfA[8][4], sfB[8][4];

  const uint32_t kaddr = sb + (uint32_t)((lane & 7) + ((lane >> 4) << 3)) * ROWB +
                         ((lane >> 3) & 1) * 16;
  const uint32_t vaddr = sb + (uint32_t)((lane & 7) + (((lane >> 3) & 1) << 3)) * ROWB +
                         ((lane >> 4) & 1) * 16 + SVHI;

  // Prologue: S(0).
  CP_WAIT2();        // group 0 done (outstanding: 1, 2)
  __syncthreads();
  s_mma_tile(sfA, kaddr, qh, ql);

  // Body for tile t: wait K(t+1), prefetch t+3, S(t+1)->nxt fused with
  // softmax+PV(t) on cur.
#define TILE_BODY(T, CUR, NXT)                                                \
  {                                                                           \
    CP_WAIT1();                                                               \
    __syncthreads();                                                          \
    if ((T) + 3 < FNT)                                                        \
      flash_issue(tid, nbase + ((T) + 3) * 64,                                \
                  sb + (uint32_t)(((T) + 3) & 3) * FSTAGE);                   \
    CP_COMMIT();                                                              \
    s_mma_tile(NXT, kaddr + (uint32_t)(((T) + 1) & 3) * FSTAGE, qh, ql);      \
    softmax_pv(CUR, of, mrow0, mrow1, l0, l1,                                 \
               vaddr + (uint32_t)((T) & 3) * FSTAGE);                         \
  }

  for (int tp = 0; tp < (FNT - 2) / 2; tp++) {     // 31 pairs: t = 0..61
    TILE_BODY(2 * tp, sfA, sfB);
    TILE_BODY(2 * tp + 1, sfB, sfA);
  }
  TILE_BODY(FNT - 2, sfA, sfB);                    // t = 62 (S(63) -> sfB)
  // Tail: tile 63 (resident in stage 3).
  softmax_pv(sfB, of, mrow0, mrow1, l0, l1,
             vaddr + (uint32_t)((FNT - 1) & 3) * FSTAGE);
#undef TILE_BODY

  // ---- write partials ----
  int r0 = lane >> 2, r1 = r0 + 8;
  int cbase = 2 * (lane & 3);
  size_t orow0 = (size_t)(split * NTOK + mb + wm + r0) * DH;
  size_t orow1 = (size_t)(split * NTOK + mb + wm + r1) * DH;
#pragma unroll
  for (int f = 0; f < 16; f++) {
    *(float2*)&g_Opart[orow0 + 8 * f + cbase] = make_float2(of[f][0], of[f][1]);
    *(float2*)&g_Opart[orow1 + 8 * f + cbase] = make_float2(of[f][2], of[f][3]);
  }
  if ((lane & 3) == 0) {
    g_Mpart[split * NTOK + mb + wm + r0] = mrow0;
    g_Lpart[split * NTOK + mb + wm + r0] = l0;
    g_Mpart[split * NTOK + mb + wm + r1] = mrow1;
    g_Lpart[split * NTOK + mb + wm + r1] = l1;
  }
}

// ---------------------------------------------------------------------------
// Kernel 3: split-KV merge.
// ---------------------------------------------------------------------------
__global__ __launch_bounds__(256) void merge_kernel(float* __restrict__ out) {
  const int tid = threadIdx.x;
  const int row = blockIdx.x * 8 + (tid >> 5);
  const int c4 = (tid & 31) * 4;

  float ma = g_Mpart[row], la = g_Lpart[row];
  float mb2 = g_Mpart[NTOK + row], lb = g_Lpart[NTOK + row];
  float M = fmaxf(ma, mb2);
  float wa = ex2f(ma - M), wb = ex2f(mb2 - M);
  float inv = 1.0f / (wa * la + wb * lb);

  float4 oa = *(const float4*)&g_Opart[(size_t)row * DH + c4];
  float4 ob = *(const float4*)&g_Opart[(size_t)(NTOK + row) * DH + c4];
  float4 r;
  r.x = (wa * oa.x + wb * ob.x) * inv;
  r.y = (wa * oa.y + wb * ob.y) * inv;
  r.z = (wa * oa.z + wb * ob.z) * inv;
  r.w = (wa * oa.w + wb * ob.w) * inv;
  *(float4*)&out[(size_t)row * DH + c4] = r;
}

// ---------------------------------------------------------------------------
extern "C" void kernel_launch(void* const* d_in, const int* in_sizes, int n_in,
                              void* d_out, int out_size) {
  const float* x  = (const float*)d_in[0];
  const float* Wq = (const float*)d_in[1];
  const float* Wk = (const float*)d_in[2];
  const float* Wv = (const float*)d_in[3];
  float* out = (float*)d_out;

  split_x_kernel<<<NTOK * DIN / 1024, 256>>>(x);
  split_w_kernel<<<dim3(DIN * DH / 1024, 3, 1), 256>>>(Wq, Wk, Wv);

  cudaFuncSetAttribute(qkv_proj_mma, cudaFuncAttributeMaxDynamicSharedMemorySize,
                       SMEM_PROJ);
  qkv_proj_mma<<<dim3(NTOK / 128, 3, 1), 256, SMEM_PROJ>>>();

  cudaFuncSetAttribute(flash_mma, cudaFuncAttributeMaxDynamicSharedMemorySize,
                       SMEM_FLASH);
  flash_mma<<<dim3(NTOK / 128, NSPLIT, 1), 256, SMEM_FLASH>>>(0);

  merge_kernel<<<NTOK / 8, 256>>>(out);
}

// round 7
// speedup vs baseline: 5.5238x; 1.0230x over previous
#include <cuda_runtime.h>
#include <cuda_bf16.h>
#include <cuda_fp16.h>
#include <cstdint>

#define NTOK 8192
#define DIN  1024
#define DH   128
#define NSPLIT 2
#define KEYS_PER_SPLIT (NTOK / NSPLIT)

// Pre-split inputs (prep kernels).
__device__ __nv_bfloat16 g_Xhi[NTOK * DIN], g_Xlo[NTOK * DIN];
__device__ __nv_bfloat16 g_Whi[3 * DIN * DH], g_Wlo[3 * DIN * DH];
// Split operands produced by the projection kernel.
__device__ __nv_bfloat16 g_Qhi[NTOK * DH], g_Qlo[NTOK * DH]; // pre-scaled by (1/sqrt d)*log2 e
__device__ __nv_bfloat16 g_Khi[NTOK * DH], g_Klo[NTOK * DH];
__device__ __half        g_Vhi[NTOK * DH];
// Split-KV partials.
__device__ float g_Opart[NSPLIT * NTOK * DH];
__device__ float g_Mpart[NSPLIT * NTOK];
__device__ float g_Lpart[NSPLIT * NTOK];

__device__ __forceinline__ uint32_t smem_u32(const void* p) {
  uint32_t a;
  asm("{ .reg .u64 t; cvta.to.shared.u64 t, %1; cvt.u32.u64 %0, t; }"
      : "=r"(a) : "l"(p));
  return a;
}
__device__ __forceinline__ float ex2f(float x) {
  float y; asm("ex2.approx.ftz.f32 %0, %1;" : "=f"(y) : "f"(x)); return y;
}
__device__ __forceinline__ void ldsm4(uint32_t* r, uint32_t addr) {
  asm volatile("ldmatrix.sync.aligned.m8n8.x4.shared.b16 {%0,%1,%2,%3}, [%4];"
               : "=r"(r[0]), "=r"(r[1]), "=r"(r[2]), "=r"(r[3]) : "r"(addr));
}
__device__ __forceinline__ void ldsm4t(uint32_t* r, uint32_t addr) {
  asm volatile("ldmatrix.sync.aligned.m8n8.x4.trans.shared.b16 {%0,%1,%2,%3}, [%4];"
               : "=r"(r[0]), "=r"(r[1]), "=r"(r[2]), "=r"(r[3]) : "r"(addr));
}
__device__ __forceinline__ void mma_bf16(float* d, const uint32_t* a,
                                         const uint32_t* b) {
  asm volatile(
      "mma.sync.aligned.m16n8k16.row.col.f32.bf16.bf16.f32 "
      "{%0,%1,%2,%3}, {%4,%5,%6,%7}, {%8,%9}, {%0,%1,%2,%3};"
      : "+f"(d[0]), "+f"(d[1]), "+f"(d[2]), "+f"(d[3])
      : "r"(a[0]), "r"(a[1]), "r"(a[2]), "r"(a[3]), "r"(b[0]), "r"(b[1]));
}
__device__ __forceinline__ void mma_f16(float* d, const uint32_t* a,
                                        const uint32_t* b) {
  asm volatile(
      "mma.sync.aligned.m16n8k16.row.col.f32.f16.f16.f32 "
      "{%0,%1,%2,%3}, {%4,%5,%6,%7}, {%8,%9}, {%0,%1,%2,%3};"
      : "+f"(d[0]), "+f"(d[1]), "+f"(d[2]), "+f"(d[3])
      : "r"(a[0]), "r"(a[1]), "r"(a[2]), "r"(a[3]), "r"(b[0]), "r"(b[1]));
}
__device__ __forceinline__ void cpa16(uint32_t dst, const void* src) {
  asm volatile("cp.async.cg.shared.global [%0], [%1], 16;" :: "r"(dst), "l"(src));
}
#define CP_COMMIT() asm volatile("cp.async.commit_group;" ::: "memory")
#define CP_WAIT1() asm volatile("cp.async.wait_group 1;" ::: "memory")
#define CP_WAIT0() asm volatile("cp.async.wait_group 0;" ::: "memory")

// ---------------------------------------------------------------------------
// Prep kernels: split fp32 -> bf16 hi/lo.
// ---------------------------------------------------------------------------
__global__ __launch_bounds__(256) void split_x_kernel(const float* __restrict__ x) {
  size_t i = ((size_t)blockIdx.x * 256 + threadIdx.x) * 4;
  float4 v = *(const float4*)(x + i);
  __nv_bfloat16 h0 = __float2bfloat16_rn(v.x), h1 = __float2bfloat16_rn(v.y);
  __nv_bfloat16 h2 = __float2bfloat16_rn(v.z), h3 = __float2bfloat16_rn(v.w);
  __nv_bfloat162 hh0 = __halves2bfloat162(h0, h1), hh1 = __halves2bfloat162(h2, h3);
  __nv_bfloat162 ll0 = __halves2bfloat162(
      __float2bfloat16_rn(v.x - __bfloat162float(h0)),
      __float2bfloat16_rn(v.y - __bfloat162float(h1)));
  __nv_bfloat162 ll1 = __halves2bfloat162(
      __float2bfloat16_rn(v.z - __bfloat162float(h2)),
      __float2bfloat16_rn(v.w - __bfloat162float(h3)));
  *(uint2*)&g_Xhi[i] = make_uint2(*(uint32_t*)&hh0, *(uint32_t*)&hh1);
  *(uint2*)&g_Xlo[i] = make_uint2(*(uint32_t*)&ll0, *(uint32_t*)&ll1);
}

__global__ __launch_bounds__(256) void split_w_kernel(
    const float* __restrict__ Wq, const float* __restrict__ Wk,
    const float* __restrict__ Wv) {
  const float* W;
  float sc = 1.0f;
  if (blockIdx.y == 0) { W = Wq; sc = 0.08838834764831845f * 1.4426950408889634f; }
  else if (blockIdx.y == 1) W = Wk;
  else W = Wv;
  size_t i = ((size_t)blockIdx.x * 256 + threadIdx.x) * 4;
  float4 v = *(const float4*)(W + i);
  v.x *= sc; v.y *= sc; v.z *= sc; v.w *= sc;
  __nv_bfloat16 h0 = __float2bfloat16_rn(v.x), h1 = __float2bfloat16_rn(v.y);
  __nv_bfloat16 h2 = __float2bfloat16_rn(v.z), h3 = __float2bfloat16_rn(v.w);
  __nv_bfloat162 hh0 = __halves2bfloat162(h0, h1), hh1 = __halves2bfloat162(h2, h3);
  __nv_bfloat162 ll0 = __halves2bfloat162(
      __float2bfloat16_rn(v.x - __bfloat162float(h0)),
      __float2bfloat16_rn(v.y - __bfloat162float(h1)));
  __nv_bfloat162 ll1 = __halves2bfloat162(
      __float2bfloat16_rn(v.z - __bfloat162float(h2)),
      __float2bfloat16_rn(v.w - __bfloat162float(h3)));
  size_t o = (size_t)blockIdx.y * DIN * DH + i;
  *(uint2*)&g_Whi[o] = make_uint2(*(uint32_t*)&hh0, *(uint32_t*)&hh1);
  *(uint2*)&g_Wlo[o] = make_uint2(*(uint32_t*)&ll0, *(uint32_t*)&ll1);
}

// ---------------------------------------------------------------------------
// Kernel 1: QKV projection GEMM on pre-split bf16, cp.async double-buffered.
// ---------------------------------------------------------------------------
#define XROW 144
#define WROW 272
#define PSTAGE 71680
#define SMEM_PROJ (2 * PSTAGE)

__device__ __forceinline__ void proj_issue(int tid, int mb, int y, int k0,
                                           uint32_t dstbase) {
#pragma unroll
  for (int it = 0; it < 8; it++) {
    int idx = tid + it * 256;
    int arr = idx >> 10, w = idx & 1023;
    int r = w >> 3, c = w & 7;
    const __nv_bfloat16* src = (arr ? g_Xlo : g_Xhi) +
                               (size_t)(mb + r) * DIN + k0 + c * 8;
    cpa16(dstbase + arr * 18432 + r * XROW + c * 16, src);
  }
#pragma unroll
  for (int it = 0; it < 8; it++) {
    int idx = tid + it * 256;
    int arr = idx >> 10, w = idx & 1023;
    int r = w >> 4, c = w & 15;
    const __nv_bfloat16* src = (arr ? g_Wlo : g_Whi) +
                               (size_t)y * DIN * DH + (size_t)(k0 + r) * DH + c * 8;
    cpa16(dstbase + 36864 + arr * 17408 + r * WROW + c * 16, src);
  }
}

__global__ __launch_bounds__(256, 1) void qkv_proj_mma() {
  extern __shared__ char smc[];
  const int tid = threadIdx.x;
  const int lane = tid & 31, warp = tid >> 5;
  const int wm = warp * 16;
  const int mb = blockIdx.x * 128;
  const int y = blockIdx.y;
  const uint32_t sb = smem_u32(smc);

  float acc[16][4];
#pragma unroll
  for (int f = 0; f < 16; f++)
#pragma unroll
    for (int e = 0; e < 4; e++) acc[f][e] = 0.f;

  const uint32_t ah_addr = sb + (uint32_t)(wm + (lane & 15)) * XROW +
                           (lane >> 4) * 16;
  const uint32_t bh_addr = sb + 36864 +
                           (uint32_t)((lane & 7) + ((lane >> 3) & 1) * 8) * WROW +
                           ((lane >> 4) & 1) * 16;

  proj_issue(tid, mb, y, 0, sb);          CP_COMMIT();
  proj_issue(tid, mb, y, 64, sb + PSTAGE); CP_COMMIT();

  const int NT = DIN / 64;   // 16
  for (int t = 0; t < NT; t++) {
    if (t + 1 < NT) CP_WAIT1(); else CP_WAIT0();
    __syncthreads();
    uint32_t bo = (uint32_t)(t & 1) * PSTAGE;
#pragma unroll
    for (int j = 0; j < 4; j++) {
      uint32_t ah[4], al[4];
      ldsm4(ah, ah_addr + bo + j * 32);
      ldsm4(al, ah_addr + bo + 18432 + j * 32);
#pragma unroll
      for (int f2 = 0; f2 < 8; f2++) {
        uint32_t bh[4], bl[4];
        uint32_t a = bh_addr + bo + (uint32_t)(j * 16) * WROW + f2 * 32;
        ldsm4t(bh, a);
        ldsm4t(bl, a + 17408);
        mma_bf16(acc[2 * f2], ah, bh);
        mma_bf16(acc[2 * f2 + 1], ah, bh + 2);
        mma_bf16(acc[2 * f2], ah, bl);
        mma_bf16(acc[2 * f2 + 1], ah, bl + 2);
        mma_bf16(acc[2 * f2], al, bh);
        mma_bf16(acc[2 * f2 + 1], al, bh + 2);
      }
    }
    __syncthreads();
    if (t + 2 < NT) { proj_issue(tid, mb, y, (t + 2) * 64, sb + bo); }
    CP_COMMIT();
  }

  // Epilogue: emit split operands (Q pre-scaled via Wq split; V fp16 hi only).
  int r0 = mb + wm + (lane >> 2), r1 = r0 + 8;
  int cb = 2 * (lane & 3);
#pragma unroll
  for (int f = 0; f < 16; f++) {
    int c = 8 * f + cb;
    float v0 = acc[f][0], v1 = acc[f][1], v2 = acc[f][2], v3 = acc[f][3];
    if (y == 2) {
      *(__half2*)&g_Vhi[(size_t)r0 * DH + c] = __floats2half2_rn(v0, v1);
      *(__half2*)&g_Vhi[(size_t)r1 * DH + c] = __floats2half2_rn(v2, v3);
    } else {
      __nv_bfloat16 h0 = __float2bfloat16_rn(v0), h1 = __float2bfloat16_rn(v1);
      __nv_bfloat16 h2 = __float2bfloat16_rn(v2), h3 = __float2bfloat16_rn(v3);
      __nv_bfloat16* hi = y ? g_Khi : g_Qhi;
      __nv_bfloat16* lo = y ? g_Klo : g_Qlo;
      *(__nv_bfloat162*)&hi[(size_t)r0 * DH + c] = __halves2bfloat162(h0, h1);
      *(__nv_bfloat162*)&hi[(size_t)r1 * DH + c] = __halves2bfloat162(h2, h3);
      *(__nv_bfloat162*)&lo[(size_t)r0 * DH + c] = __halves2bfloat162(
          __float2bfloat16_rn(v0 - __bfloat162float(h0)),
          __float2bfloat16_rn(v1 - __bfloat162float(h1)));
      *(__nv_bfloat162*)&lo[(size_t)r1 * DH + c] = __halves2bfloat162(
          __float2bfloat16_rn(v2 - __bfloat162float(h2)),
          __float2bfloat16_rn(v3 - __bfloat162float(h3)));
    }
  }
}

// ---------------------------------------------------------------------------
// Kernel 2: flash attention, BM=128 (8 warps), BN=64, split-KV x2.
// 3-stage cp.async ring + resident Q in dedicated smem (Q fragments re-LDSM'd
// per tile -> 64 fewer registers -> fused S(t+1) / softmax+PV(t) schedules
// without spills).  PV = Phi * Vhi (fp16).  Alpha-skip on O rescale.
// Stage: KHI 0, KLO 17408, VHI 34816; size 52224; 3 stages.
// Q area at 156672: Qhi [128x272]=34816, Qlo at +34816.  Total 226304 B.
// ---------------------------------------------------------------------------
#define ROWB 272
#define SKLO 17408
#define SVHI 34816
#define FSTAGE 52224
#define QOFF (3 * FSTAGE)
#define QLO_OFF 34816
#define SMEM_FLASH (QOFF + 2 * 34816)
#define FNT (KEYS_PER_SPLIT / 64)   // 64 tiles

__device__ __forceinline__ void flash_issue(int tid, int n0, uint32_t dstbase) {
#pragma unroll
  for (int arr = 0; arr < 3; arr++) {
    const __nv_bfloat16* srcb;
    if (arr == 0)      srcb = g_Khi;
    else if (arr == 1) srcb = g_Klo;
    else               srcb = (const __nv_bfloat16*)g_Vhi;
#pragma unroll
    for (int it = 0; it < 4; it++) {
      int idx = tid + it * 256;
      int r = idx >> 4, c = idx & 15;
      cpa16(dstbase + arr * 17408 + r * ROWB + c * 16,
            srcb + (size_t)(n0 + r) * DH + c * 8);
    }
  }
}

// S = Q K^T for one key tile (Q fragments re-loaded from resident smem).
__device__ __forceinline__ void s_mma_tile(float sf[8][4], uint32_t kbase,
                                           uint32_t qh_addr, uint32_t ql_addr) {
#pragma unroll
  for (int f = 0; f < 8; f++)
#pragma unroll
    for (int e = 0; e < 4; e++) sf[f][e] = 0.f;
#pragma unroll
  for (int j = 0; j < 8; j++) {
    uint32_t qh[4], ql[4];
    ldsm4(qh, qh_addr + j * 32);
    ldsm4(ql, ql_addr + j * 32);
#pragma unroll
    for (int f2 = 0; f2 < 4; f2++) {
      uint32_t bh[4], bl[4];
      uint32_t a = kbase + (uint32_t)(f2 * 16) * ROWB + j * 32;
      ldsm4(bh, a);
      ldsm4(bl, a + SKLO);
      mma_bf16(sf[2 * f2], qh, bh);
      mma_bf16(sf[2 * f2 + 1], qh, bh + 2);
      mma_bf16(sf[2 * f2], qh, bl);
      mma_bf16(sf[2 * f2 + 1], qh, bl + 2);
      mma_bf16(sf[2 * f2], ql, bh);
      mma_bf16(sf[2 * f2 + 1], ql, bh + 2);
    }
  }
}

// Online softmax (base-2 logits) + conditional O rescale + PV accumulate.
__device__ __forceinline__ void softmax_pv(float sf[8][4], float of[16][4],
                                           float& mrow0, float& mrow1,
                                           float& l0, float& l1,
                                           uint32_t vbase) {
  float mx0 = sf[0][0], mx1 = sf[0][2];
#pragma unroll
  for (int f = 0; f < 8; f++) {
    mx0 = fmaxf(mx0, fmaxf(sf[f][0], sf[f][1]));
    mx1 = fmaxf(mx1, fmaxf(sf[f][2], sf[f][3]));
  }
  mx0 = fmaxf(mx0, __shfl_xor_sync(0xffffffffu, mx0, 1));
  mx0 = fmaxf(mx0, __shfl_xor_sync(0xffffffffu, mx0, 2));
  mx1 = fmaxf(mx1, __shfl_xor_sync(0xffffffffu, mx1, 1));
  mx1 = fmaxf(mx1, __shfl_xor_sync(0xffffffffu, mx1, 2));

  float mn0 = fmaxf(mrow0, mx0), mn1 = fmaxf(mrow1, mx1);
  float a0 = ex2f(mrow0 - mn0), a1 = ex2f(mrow1 - mn1);
  mrow0 = mn0; mrow1 = mn1;

  float s0 = 0.f, s1 = 0.f;
#pragma unroll
  for (int f = 0; f < 8; f++) {
    sf[f][0] = ex2f(sf[f][0] - mn0);
    sf[f][1] = ex2f(sf[f][1] - mn0);
    sf[f][2] = ex2f(sf[f][2] - mn1);
    sf[f][3] = ex2f(sf[f][3] - mn1);
    s0 += sf[f][0] + sf[f][1];
    s1 += sf[f][2] + sf[f][3];
  }
  s0 += __shfl_xor_sync(0xffffffffu, s0, 1);
  s0 += __shfl_xor_sync(0xffffffffu, s0, 2);
  s1 += __shfl_xor_sync(0xffffffffu, s1, 1);
  s1 += __shfl_xor_sync(0xffffffffu, s1, 2);
  l0 = l0 * a0 + s0;
  l1 = l1 * a1 + s1;

  // Rescale only when some row max changed anywhere in the warp.
  if (!__all_sync(0xffffffffu, (__float_as_uint(a0) == 0x3f800000u) &&
                              (__float_as_uint(a1) == 0x3f800000u))) {
#pragma unroll
    for (int f = 0; f < 16; f++) {
      of[f][0] *= a0;  of[f][1] *= a0;
      of[f][2] *= a1;  of[f][3] *= a1;
    }
  }

#pragma unroll
  for (int j2 = 0; j2 < 4; j2++) {
    uint32_t ph[4];
    __half2 h;
    h = __floats2half2_rn(sf[2 * j2][0], sf[2 * j2][1]);         ph[0] = *(uint32_t*)&h;
    h = __floats2half2_rn(sf[2 * j2][2], sf[2 * j2][3]);         ph[1] = *(uint32_t*)&h;
    h = __floats2half2_rn(sf[2 * j2 + 1][0], sf[2 * j2 + 1][1]); ph[2] = *(uint32_t*)&h;
    h = __floats2half2_rn(sf[2 * j2 + 1][2], sf[2 * j2 + 1][3]); ph[3] = *(uint32_t*)&h;
    uint32_t ka = vbase + (uint32_t)(j2 * 16) * ROWB;
#pragma unroll
    for (int f2 = 0; f2 < 8; f2++) {
      uint32_t bv[4];
      ldsm4t(bv, ka + f2 * 32);
      mma_f16(of[2 * f2], ph, bv);
      mma_f16(of[2 * f2 + 1], ph, bv + 2);
    }
  }
}

__global__ __launch_bounds__(256, 1) void flash_mma(int dummy) {
  extern __shared__ char smc[];
  const int tid = threadIdx.x;
  const int lane = tid & 31, warp = tid >> 5;
  const int wm = warp * 16;
  const int mb = blockIdx.x * 128;
  const int split = blockIdx.y;
  const int nbase = split * KEYS_PER_SPLIT;
  const uint32_t sb = smem_u32(smc);

  // Prefetch tiles 0 and 1.
  flash_issue(tid, nbase, sb);                 CP_COMMIT();   // group 0
  flash_issue(tid, nbase + 64, sb + FSTAGE);   CP_COMMIT();   // group 1

  // Stage Q into the dedicated area.
#pragma unroll
  for (int it = 0; it < 8; it++) {
    int idx = tid + it * 256;
    int r = idx >> 4, c = idx & 15;
    size_t g = (size_t)(mb + r) * DH + c * 8;
    *(float4*)(smc + QOFF + r * ROWB + c * 16) = *(const float4*)(g_Qhi + g);
    *(float4*)(smc + QOFF + QLO_OFF + r * ROWB + c * 16) = *(const float4*)(g_Qlo + g);
  }

  const uint32_t qh_addr = sb + QOFF + (uint32_t)(wm + (lane & 15)) * ROWB +
                           (lane >> 4) * 16;
  const uint32_t ql_addr = qh_addr + QLO_OFF;
  const uint32_t kaddr = sb + (uint32_t)((lane & 7) + ((lane >> 4) << 3)) * ROWB +
                         ((lane >> 3) & 1) * 16;
  const uint32_t vaddr = sb + (uint32_t)((lane & 7) + (((lane >> 3) & 1) << 3)) * ROWB +
                         ((lane >> 4) & 1) * 16 + SVHI;

  float of[16][4];
#pragma unroll
  for (int f = 0; f < 16; f++)
#pragma unroll
    for (int e = 0; e < 4; e++) of[f][e] = 0.f;
  float mrow0 = -1e30f, mrow1 = -1e30f, l0 = 0.f, l1 = 0.f;
  float sfA[8][4], sfB[8][4];

  // Prologue: S(0) from stage 0.
  CP_WAIT1();          // group 0 complete (group 1 outstanding)
  __syncthreads();     // Q staged + stage-0 data visible to all warps
  s_mma_tile(sfA, kaddr, qh_addr, ql_addr);

  // Body t: wait K(t+1); barrier releases V(t-1)'s stage and publishes
  // K(t+1); prefetch tile t+2 into stage (t+2)%3; then fused
  // S(t+1) [NXT] + softmax+PV(t) [CUR].
#define TILE_BODY(T, CUR, NXT)                                                \
  {                                                                           \
    CP_WAIT0();                                                               \
    __syncthreads();                                                          \
    if ((T) + 2 < FNT) {                                                      \
      flash_issue(tid, nbase + ((T) + 2) * 64,                                \
                  sb + (uint32_t)(((T) + 2) % 3) * FSTAGE);                   \
      CP_COMMIT();                                                            \
    }                                                                         \
    s_mma_tile(NXT, kaddr + (uint32_t)((((T) + 1) % 3)) * FSTAGE,             \
               qh_addr, ql_addr);                                             \
    softmax_pv(CUR, of, mrow0, mrow1, l0, l1,                                 \
               vaddr + (uint32_t)((T) % 3) * FSTAGE);                         \
  }

  for (int tp = 0; tp < (FNT - 2) / 2; tp++) {     // t = 0..61
    TILE_BODY(2 * tp, sfA, sfB);
    TILE_BODY(2 * tp + 1, sfB, sfA);
  }
  TILE_BODY(FNT - 2, sfA, sfB);                    // t = 62 (S(63) -> sfB)
  softmax_pv(sfB, of, mrow0, mrow1, l0, l1,
             vaddr + (uint32_t)((FNT - 1) % 3) * FSTAGE);
#undef TILE_BODY

  // ---- write partials ----
  int r0 = lane >> 2, r1 = r0 + 8;
  int cbase = 2 * (lane & 3);
  size_t orow0 = (size_t)(split * NTOK + mb + wm + r0) * DH;
  size_t orow1 = (size_t)(split * NTOK + mb + wm + r1) * DH;
#pragma unroll
  for (int f = 0; f < 16; f++) {
    *(float2*)&g_Opart[orow0 + 8 * f + cbase] = make_float2(of[f][0], of[f][1]);
    *(float2*)&g_Opart[orow1 + 8 * f + cbase] = make_float2(of[f][2], of[f][3]);
  }
  if ((lane & 3) == 0) {
    g_Mpart[split * NTOK + mb + wm + r0] = mrow0;
    g_Lpart[split * NTOK + mb + wm + r0] = l0;
    g_Mpart[split * NTOK + mb + wm + r1] = mrow1;
    g_Lpart[split * NTOK + mb + wm + r1] = l1;
  }
}

// ---------------------------------------------------------------------------
// Kernel 3: split-KV merge.
// ---------------------------------------------------------------------------
__global__ __launch_bounds__(256) void merge_kernel(float* __restrict__ out) {
  const int tid = threadIdx.x;
  const int row = blockIdx.x * 8 + (tid >> 5);
  const int c4 = (tid & 31) * 4;

  float ma = g_Mpart[row], la = g_Lpart[row];
  float mb2 = g_Mpart[NTOK + row], lb = g_Lpart[NTOK + row];
  float M = fmaxf(ma, mb2);
  float wa = ex2f(ma - M), wb = ex2f(mb2 - M);
  float inv = 1.0f / (wa * la + wb * lb);

  float4 oa = *(const float4*)&g_Opart[(size_t)row * DH + c4];
  float4 ob = *(const float4*)&g_Opart[(size_t)(NTOK + row) * DH + c4];
  float4 r;
  r.x = (wa * oa.x + wb * ob.x) * inv;
  r.y = (wa * oa.y + wb * ob.y) * inv;
  r.z = (wa * oa.z + wb * ob.z) * inv;
  r.w = (wa * oa.w + wb * ob.w) * inv;
  *(float4*)&out[(size_t)row * DH + c4] = r;
}

// ---------------------------------------------------------------------------
extern "C" void kernel_launch(void* const* d_in, const int* in_sizes, int n_in,
                              void* d_out, int out_size) {
  const float* x  = (const float*)d_in[0];
  const float* Wq = (const float*)d_in[1];
  const float* Wk = (const float*)d_in[2];
  const float* Wv = (const float*)d_in[3];
  float* out = (float*)d_out;

  split_x_kernel<<<NTOK * DIN / 1024, 256>>>(x);
  split_w_kernel<<<dim3(DIN * DH / 1024, 3, 1), 256>>>(Wq, Wk, Wv);

  cudaFuncSetAttribute(qkv_proj_mma, cudaFuncAttributeMaxDynamicSharedMemorySize,
                       SMEM_PROJ);
  qkv_proj_mma<<<dim3(NTOK / 128, 3, 1), 256, SMEM_PROJ>>>();

  cudaFuncSetAttribute(flash_mma, cudaFuncAttributeMaxDynamicSharedMemorySize,
                       SMEM_FLASH);
  flash_mma<<<dim3(NTOK / 128, NSPLIT, 1), 256, SMEM_FLASH>>>(0);

  merge_kernel<<<NTOK / 8, 256>>>(out);
}